// round 2
// baseline (speedup 1.0000x reference)
#include <cuda_runtime.h>
#include <math.h>

#define N_NODES 10000
#define N_EDGES 320000
#define IN_DIM  10000
#define HID     128
#define NCLS    2

// Scratch (no allocs allowed) -------------------------------------------------
__device__ float g_h[(size_t)N_NODES * HID];     // x @ W_conv
__device__ float g_agg[(size_t)N_NODES * HID];   // aggregated messages
__device__ float g_deg[N_NODES];
__device__ float g_dinv[N_NODES];
__device__ int   g_is32;                         // edge_index dtype flag

// --- edge_index dtype detection ---------------------------------------------
// int64 node indices are in [0, 10000) -> high 32 bits zero. If the buffer is
// actually int32, reading it as int64 merges two random indices -> out of range.
__global__ void k_detect(const long long* ei) {
    if (threadIdx.x == 0 && blockIdx.x == 0) {
        int is32 = 0;
        for (int i = 0; i < 16; i++) {
            long long v = ei[i];
            if (v < 0 || v >= N_NODES) { is32 = 1; break; }
        }
        g_is32 = is32;
    }
}

__device__ __forceinline__ int edge_idx(const void* ei, long long i) {
    if (g_is32) return ((const int*)ei)[i];
    return (int)((const long long*)ei)[i];
}

// --- degree ------------------------------------------------------------------
__global__ void k_deg_init() {
    int i = blockIdx.x * blockDim.x + threadIdx.x;
    if (i < N_NODES) g_deg[i] = 1.0f;   // self-loop weight
}

__global__ void k_deg_accum(const void* ei, const float* __restrict__ ew) {
    int e = blockIdx.x * blockDim.x + threadIdx.x;
    if (e < N_EDGES) {
        int c = edge_idx(ei, (long long)N_EDGES + e);   // col
        atomicAdd(&g_deg[c], ew[e]);
    }
}

__global__ void k_dinv() {
    int i = blockIdx.x * blockDim.x + threadIdx.x;
    if (i < N_NODES) {
        float d = g_deg[i];
        g_dinv[i] = (d > 0.0f) ? rsqrtf(d) : 0.0f;
    }
}

// --- GEMM: h = x @ W_conv  (M=10000, K=10000, N=128) -------------------------
#define BM 64
#define BN 128
#define BK 16

__global__ __launch_bounds__(256) void k_gemm(const float* __restrict__ x,
                                              const float* __restrict__ W) {
    __shared__ float xs[BK][BM + 1];   // transposed x tile (k-major)
    __shared__ float ws[BK][BN];

    const int tid = threadIdx.x;
    const int m0  = blockIdx.x * BM;
    const int ty  = tid >> 4;          // 0..15
    const int tx  = tid & 15;          // 0..15

    float acc[4][8];
#pragma unroll
    for (int i = 0; i < 4; i++)
#pragma unroll
        for (int j = 0; j < 8; j++) acc[i][j] = 0.0f;

    const int lr = tid >> 2;           // 0..63 (row within tile)
    const int lc = tid & 3;            // 0..3  (float4 within BK)
    const int gm = m0 + lr;
    const float* xrow = x + (size_t)gm * IN_DIM;

    for (int k0 = 0; k0 < IN_DIM; k0 += BK) {
        float4 xv = make_float4(0.f, 0.f, 0.f, 0.f);
        if (gm < N_NODES) xv = *(const float4*)(xrow + k0 + lc * 4);
        xs[lc * 4 + 0][lr] = xv.x;
        xs[lc * 4 + 1][lr] = xv.y;
        xs[lc * 4 + 2][lr] = xv.z;
        xs[lc * 4 + 3][lr] = xv.w;
#pragma unroll
        for (int q = 0; q < 2; q++) {
            int lin = tid + 256 * q;
            int wr = lin >> 5, wc = lin & 31;
            *(float4*)&ws[wr][wc * 4] =
                *(const float4*)&W[(size_t)(k0 + wr) * HID + wc * 4];
        }
        __syncthreads();

#pragma unroll
        for (int k = 0; k < BK; k++) {
            float a[4];
#pragma unroll
            for (int i = 0; i < 4; i++) a[i] = xs[k][ty * 4 + i];
            float4 b0 = *(float4*)&ws[k][tx * 8];
            float4 b1 = *(float4*)&ws[k][tx * 8 + 4];
            float b[8] = {b0.x, b0.y, b0.z, b0.w, b1.x, b1.y, b1.z, b1.w};
#pragma unroll
            for (int i = 0; i < 4; i++)
#pragma unroll
                for (int j = 0; j < 8; j++) acc[i][j] += a[i] * b[j];
        }
        __syncthreads();
    }

#pragma unroll
    for (int i = 0; i < 4; i++) {
        int gr = m0 + ty * 4 + i;
        if (gr < N_NODES) {
            float* hp = g_h + (size_t)gr * HID + tx * 8;
            *(float4*)hp       = make_float4(acc[i][0], acc[i][1], acc[i][2], acc[i][3]);
            *(float4*)(hp + 4) = make_float4(acc[i][4], acc[i][5], acc[i][6], acc[i][7]);
        }
    }
}

// --- self-loop init: agg[i] = dinv[i]^2 * h[i] (also initializes agg) --------
__global__ void k_selfloop() {
    int idx = blockIdx.x * blockDim.x + threadIdx.x;
    if (idx < N_NODES * HID) {
        int i = idx >> 7;   // / HID
        float d = g_dinv[i];
        g_agg[idx] = d * d * g_h[idx];
    }
}

// --- edge scatter: one warp per edge, float4 gather + 4 atomics --------------
__global__ __launch_bounds__(256) void k_scatter(const void* ei,
                                                 const float* __restrict__ ew) {
    int gw   = blockIdx.x * 8 + (threadIdx.x >> 5);
    int lane = threadIdx.x & 31;
    if (gw >= N_EDGES) return;
    int r = edge_idx(ei, gw);                          // row (source)
    int c = edge_idx(ei, (long long)N_EDGES + gw);     // col (dest)
    float w = g_dinv[r] * ew[gw] * g_dinv[c];
    float4 v = ((const float4*)(g_h + (size_t)r * HID))[lane];
    float* ap = g_agg + (size_t)c * HID + lane * 4;
    atomicAdd(ap + 0, w * v.x);
    atomicAdd(ap + 1, w * v.y);
    atomicAdd(ap + 2, w * v.z);
    atomicAdd(ap + 3, w * v.w);
}

// --- head: relu(agg + b_conv) @ W_lin + b_lin, softmax -----------------------
__global__ __launch_bounds__(256) void k_head(const float* __restrict__ b_conv,
                                              const float* __restrict__ W_lin,
                                              const float* __restrict__ b_lin,
                                              float* __restrict__ out) {
    int i    = blockIdx.x * 8 + (threadIdx.x >> 5);
    int lane = threadIdx.x & 31;
    if (i >= N_NODES) return;

    float4 v = ((const float4*)(g_agg + (size_t)i * HID))[lane];
    float4 b = ((const float4*)b_conv)[lane];
    v.x = fmaxf(v.x + b.x, 0.0f);
    v.y = fmaxf(v.y + b.y, 0.0f);
    v.z = fmaxf(v.z + b.z, 0.0f);
    v.w = fmaxf(v.w + b.w, 0.0f);

    int k = lane * 4;
    float l0 = v.x * W_lin[(k + 0) * 2 + 0] + v.y * W_lin[(k + 1) * 2 + 0] +
               v.z * W_lin[(k + 2) * 2 + 0] + v.w * W_lin[(k + 3) * 2 + 0];
    float l1 = v.x * W_lin[(k + 0) * 2 + 1] + v.y * W_lin[(k + 1) * 2 + 1] +
               v.z * W_lin[(k + 2) * 2 + 1] + v.w * W_lin[(k + 3) * 2 + 1];

#pragma unroll
    for (int off = 16; off > 0; off >>= 1) {
        l0 += __shfl_xor_sync(0xFFFFFFFFu, l0, off);
        l1 += __shfl_xor_sync(0xFFFFFFFFu, l1, off);
    }

    if (lane == 0) {
        l0 += b_lin[0];
        l1 += b_lin[1];
        float m  = fmaxf(l0, l1);
        float e0 = expf(l0 - m), e1 = expf(l1 - m);
        float s  = e0 + e1;
        out[i * 2 + 0] = e0 / s;
        out[i * 2 + 1] = e1 / s;
    }
}

// -----------------------------------------------------------------------------
extern "C" void kernel_launch(void* const* d_in, const int* in_sizes, int n_in,
                              void* d_out, int out_size) {
    const float* x      = (const float*)d_in[0];
    const void*  ei     = d_in[1];                  // int64 or int32 (detected)
    const float* ew     = (const float*)d_in[2];
    const float* W_conv = (const float*)d_in[3];
    const float* b_conv = (const float*)d_in[4];
    const float* W_lin  = (const float*)d_in[5];
    const float* b_lin  = (const float*)d_in[6];
    float* out = (float*)d_out;

    k_detect<<<1, 32>>>((const long long*)ei);
    k_deg_init<<<(N_NODES + 255) / 256, 256>>>();
    k_deg_accum<<<(N_EDGES + 255) / 256, 256>>>(ei, ew);
    k_dinv<<<(N_NODES + 255) / 256, 256>>>();
    k_gemm<<<(N_NODES + BM - 1) / BM, 256>>>(x, W_conv);
    k_selfloop<<<(N_NODES * HID + 255) / 256, 256>>>();
    k_scatter<<<(N_EDGES + 7) / 8, 256>>>(ei, ew);
    k_head<<<(N_NODES + 7) / 8, 256>>>(b_conv, W_lin, b_lin, out);
}

// round 5
// speedup vs baseline: 3.7510x; 3.7510x over previous
#include <cuda_runtime.h>
#include <cuda_bf16.h>
#include <math.h>
#include <stdint.h>

#define N_NODES 10000
#define N_EDGES 320000
#define IN_DIM  10000
#define HID     128
#define NCLS    2

// ---------------- scratch (no allocs allowed) --------------------------------
__device__ float g_h[(size_t)N_NODES * HID];     // x @ W_conv
__device__ float g_agg[(size_t)N_NODES * HID];   // aggregated messages
__device__ float g_deg[N_NODES];
__device__ float g_dinv[N_NODES];
__device__ int   g_is32;                         // edge_index dtype flag
__device__ __nv_bfloat16 g_Wt_hi[(size_t)HID * IN_DIM];  // W^T hi split [128][10000]
__device__ __nv_bfloat16 g_Wt_lo[(size_t)HID * IN_DIM];  // W^T lo split

// ---------------- helpers ----------------------------------------------------
__device__ __forceinline__ uint32_t smem_u32(const void* p) {
    uint32_t a;
    asm("{ .reg .u64 t; cvta.to.shared.u64 t, %1; cvt.u32.u64 %0, t; }"
        : "=r"(a) : "l"(p));
    return a;
}

#define LDSM4(r, addr)                                                         \
    asm volatile("ldmatrix.sync.aligned.m8n8.x4.shared.b16 {%0,%1,%2,%3}, [%4];" \
                 : "=r"((r)[0]), "=r"((r)[1]), "=r"((r)[2]), "=r"((r)[3])      \
                 : "r"(addr))

#define MMA16816(d, a, b0, b1)                                                 \
    asm volatile("mma.sync.aligned.m16n8k16.row.col.f32.bf16.bf16.f32 "        \
                 "{%0,%1,%2,%3}, {%4,%5,%6,%7}, {%8,%9}, {%0,%1,%2,%3};"       \
                 : "+f"((d)[0]), "+f"((d)[1]), "+f"((d)[2]), "+f"((d)[3])      \
                 : "r"((a)[0]), "r"((a)[1]), "r"((a)[2]), "r"((a)[3]),         \
                   "r"(b0), "r"(b1))

// ---------------- edge_index dtype detection ---------------------------------
__global__ void k_detect(const long long* ei) {
    if (threadIdx.x == 0 && blockIdx.x == 0) {
        int is32 = 0;
        for (int i = 0; i < 16; i++) {
            long long v = ei[i];
            if (v < 0 || v >= N_NODES) { is32 = 1; break; }
        }
        g_is32 = is32;
    }
}
__device__ __forceinline__ int edge_idx(const void* ei, long long i) {
    if (g_is32) return ((const int*)ei)[i];
    return (int)((const long long*)ei)[i];
}

// ---------------- degree -----------------------------------------------------
__global__ void k_deg_init() {
    int i = blockIdx.x * blockDim.x + threadIdx.x;
    if (i < N_NODES) g_deg[i] = 1.0f;   // self-loop weight
}
__global__ void k_deg_accum(const void* ei, const float* __restrict__ ew) {
    int e = blockIdx.x * blockDim.x + threadIdx.x;
    if (e < N_EDGES) {
        int c = edge_idx(ei, (long long)N_EDGES + e);
        atomicAdd(&g_deg[c], ew[e]);
    }
}
__global__ void k_dinv() {
    int i = blockIdx.x * blockDim.x + threadIdx.x;
    if (i < N_NODES) {
        float d = g_deg[i];
        g_dinv[i] = (d > 0.0f) ? rsqrtf(d) : 0.0f;
    }
}

// ---------------- W transpose + bf16 hi/lo split -----------------------------
__global__ __launch_bounds__(256) void k_wsplit(const float* __restrict__ W) {
    __shared__ float t[32][33];
    int kb = blockIdx.x * 32, nb = blockIdx.y * 32;
    int tx = threadIdx.x & 31, ty = threadIdx.x >> 5;   // ty 0..7
#pragma unroll
    for (int r = ty; r < 32; r += 8) {
        int k = kb + r;
        t[r][tx] = (k < IN_DIM) ? W[(size_t)k * HID + nb + tx] : 0.0f;
    }
    __syncthreads();
#pragma unroll
    for (int r = ty; r < 32; r += 8) {
        int n = nb + r;
        int k = kb + tx;
        if (k < IN_DIM) {
            float v = t[tx][r];
            __nv_bfloat16 hi = __float2bfloat16(v);
            __nv_bfloat16 lo = __float2bfloat16(v - __bfloat162float(hi));
            g_Wt_hi[(size_t)n * IN_DIM + k] = hi;
            g_Wt_lo[(size_t)n * IN_DIM + k] = lo;
        }
    }
}

// ---------------- HMMA GEMM: h = x @ W_conv (bf16x3 split) -------------------
// BM=64, BN=64, BK=32, 128 threads (4 warps in 2x2), warptile 32x32.
#define BM 64
#define BN 64
#define BK 32
#define STR 40   // padded smem row stride in bf16 elements (80 B)
#define NCH ((IN_DIM + BK - 1) / BK)   // 313

__global__ __launch_bounds__(128) void k_gemm_mma(const float* __restrict__ x) {
    __shared__ __align__(16) __nv_bfloat16 sA[2][2][BM * STR];  // [buf][hi/lo]
    __shared__ __align__(16) __nv_bfloat16 sB[2][2][BN * STR];

    const int tid  = threadIdx.x;
    const int lane = tid & 31;
    const int wid  = tid >> 5;
    const int wm   = wid >> 1;          // 0..1
    const int wn   = wid & 1;           // 0..1
    const int m0   = blockIdx.x * BM;
    const int n0   = blockIdx.y * BN;

    float acc[2][4][4];
#pragma unroll
    for (int a = 0; a < 2; a++)
#pragma unroll
        for (int b = 0; b < 4; b++)
#pragma unroll
            for (int c = 0; c < 4; c++) acc[a][b][c] = 0.0f;

    float4 pa[4];
    uint4  pbh[2], pbl[2];

#define LOADG(cc)                                                              \
    {                                                                          \
        const int k0 = (cc) * BK;                                              \
        _Pragma("unroll")                                                      \
        for (int i = 0; i < 4; i++) {                                          \
            int q = tid + 128 * i, row = q >> 3, c4 = q & 7;                   \
            int gm = m0 + row, k = k0 + c4 * 4;                                \
            pa[i] = (gm < N_NODES && k < IN_DIM)                               \
                        ? *(const float4*)(x + (size_t)gm * IN_DIM + k)        \
                        : make_float4(0.f, 0.f, 0.f, 0.f);                     \
        }                                                                      \
        _Pragma("unroll")                                                      \
        for (int i = 0; i < 2; i++) {                                          \
            int q = tid + 128 * i, row = q >> 2, c4 = q & 3;                   \
            int n = n0 + row, k = k0 + c4 * 8;                                 \
            if (k < IN_DIM) {                                                  \
                pbh[i] = *(const uint4*)(g_Wt_hi + (size_t)n * IN_DIM + k);    \
                pbl[i] = *(const uint4*)(g_Wt_lo + (size_t)n * IN_DIM + k);    \
            } else {                                                           \
                pbh[i] = make_uint4(0, 0, 0, 0);                               \
                pbl[i] = make_uint4(0, 0, 0, 0);                               \
            }                                                                  \
        }                                                                      \
    }

#define STORES(p)                                                              \
    {                                                                          \
        _Pragma("unroll")                                                      \
        for (int i = 0; i < 4; i++) {                                          \
            int q = tid + 128 * i, row = q >> 3, c4 = q & 7;                   \
            float4 v = pa[i];                                                  \
            __nv_bfloat162 h0 = __float22bfloat162_rn(make_float2(v.x, v.y));  \
            __nv_bfloat162 h1 = __float22bfloat162_rn(make_float2(v.z, v.w));  \
            float2 f0 = __bfloat1622float2(h0), f1 = __bfloat1622float2(h1);   \
            __nv_bfloat162 l0 = __float22bfloat162_rn(                         \
                make_float2(v.x - f0.x, v.y - f0.y));                          \
            __nv_bfloat162 l1 = __float22bfloat162_rn(                         \
                make_float2(v.z - f1.x, v.w - f1.y));                          \
            uint2 hh = make_uint2(*(uint32_t*)&h0, *(uint32_t*)&h1);           \
            uint2 ll = make_uint2(*(uint32_t*)&l0, *(uint32_t*)&l1);           \
            *(uint2*)&sA[p][0][row * STR + c4 * 4] = hh;                       \
            *(uint2*)&sA[p][1][row * STR + c4 * 4] = ll;                       \
        }                                                                      \
        _Pragma("unroll")                                                      \
        for (int i = 0; i < 2; i++) {                                          \
            int q = tid + 128 * i, row = q >> 2, c4 = q & 3;                   \
            *(uint4*)&sB[p][0][row * STR + c4 * 8] = pbh[i];                   \
            *(uint4*)&sB[p][1][row * STR + c4 * 8] = pbl[i];                   \
        }                                                                      \
    }

    LOADG(0);
    STORES(0);
    __syncthreads();

    const int lr = lane & 15;
    const int lc = lane >> 4;

    for (int c = 0; c < NCH; c++) {
        const int p = c & 1;
        if (c + 1 < NCH) LOADG(c + 1);

        // compute on buffer p
        const uint32_t aHi = smem_u32(&sA[p][0][0]);
        const uint32_t aLo = smem_u32(&sA[p][1][0]);
        const uint32_t bHi = smem_u32(&sB[p][0][0]);
        const uint32_t bLo = smem_u32(&sB[p][1][0]);
#pragma unroll
        for (int ks = 0; ks < 2; ks++) {
            uint32_t ah[2][4], al[2][4], bh[2][4], bl[2][4];
#pragma unroll
            for (int mi = 0; mi < 2; mi++) {
                uint32_t off = (uint32_t)((wm * 32 + mi * 16 + lr) * STR) * 2 +
                               ks * 32 + lc * 16;
                LDSM4(ah[mi], aHi + off);
                LDSM4(al[mi], aLo + off);
            }
#pragma unroll
            for (int g = 0; g < 2; g++) {
                uint32_t off = (uint32_t)((wn * 32 + g * 16 + lr) * STR) * 2 +
                               ks * 32 + lc * 16;
                LDSM4(bh[g], bHi + off);
                LDSM4(bl[g], bLo + off);
            }
#pragma unroll
            for (int mi = 0; mi < 2; mi++)
#pragma unroll
                for (int ni = 0; ni < 4; ni++) {
                    int g = ni >> 1, h = ni & 1;
                    MMA16816(acc[mi][ni], ah[mi], bh[g][h], bh[g][h + 2]);
                    MMA16816(acc[mi][ni], ah[mi], bl[g][h], bl[g][h + 2]);
                    MMA16816(acc[mi][ni], al[mi], bh[g][h], bh[g][h + 2]);
                }
        }
        __syncthreads();
        if (c + 1 < NCH) STORES((c + 1) & 1);
        __syncthreads();
    }

    // epilogue: write g_h and g_agg (self-loop pre-scaled by dinv^2)
#pragma unroll
    for (int mi = 0; mi < 2; mi++) {
#pragma unroll
        for (int half = 0; half < 2; half++) {
            int row = m0 + wm * 32 + mi * 16 + (lane >> 2) + half * 8;
            if (row < N_NODES) {
                float d2 = g_dinv[row];
                d2 *= d2;
#pragma unroll
                for (int ni = 0; ni < 4; ni++) {
                    int col = n0 + wn * 32 + ni * 8 + (lane & 3) * 2;
                    float v0 = acc[mi][ni][2 * half];
                    float v1 = acc[mi][ni][2 * half + 1];
                    size_t o = (size_t)row * HID + col;
                    *(float2*)&g_h[o]   = make_float2(v0, v1);
                    *(float2*)&g_agg[o] = make_float2(d2 * v0, d2 * v1);
                }
            }
        }
    }
#undef LOADG
#undef STORES
}

// ---------------- edge scatter: one warp per edge ----------------------------
__global__ __launch_bounds__(256) void k_scatter(const void* ei,
                                                 const float* __restrict__ ew) {
    int gw   = blockIdx.x * 8 + (threadIdx.x >> 5);
    int lane = threadIdx.x & 31;
    if (gw >= N_EDGES) return;
    int r = edge_idx(ei, gw);                          // row (source)
    int c = edge_idx(ei, (long long)N_EDGES + gw);     // col (dest)
    float w = g_dinv[r] * ew[gw] * g_dinv[c];
    float4 v = ((const float4*)(g_h + (size_t)r * HID))[lane];
    float* ap = g_agg + (size_t)c * HID + lane * 4;
    atomicAdd(ap + 0, w * v.x);
    atomicAdd(ap + 1, w * v.y);
    atomicAdd(ap + 2, w * v.z);
    atomicAdd(ap + 3, w * v.w);
}

// ---------------- head: relu(agg + b_conv) @ W_lin + b_lin, softmax ----------
__global__ __launch_bounds__(256) void k_head(const float* __restrict__ b_conv,
                                              const float* __restrict__ W_lin,
                                              const float* __restrict__ b_lin,
                                              float* __restrict__ out) {
    int i    = blockIdx.x * 8 + (threadIdx.x >> 5);
    int lane = threadIdx.x & 31;
    if (i >= N_NODES) return;

    float4 v = ((const float4*)(g_agg + (size_t)i * HID))[lane];
    float4 b = ((const float4*)b_conv)[lane];
    v.x = fmaxf(v.x + b.x, 0.0f);
    v.y = fmaxf(v.y + b.y, 0.0f);
    v.z = fmaxf(v.z + b.z, 0.0f);
    v.w = fmaxf(v.w + b.w, 0.0f);

    int k = lane * 4;
    float l0 = v.x * W_lin[(k + 0) * 2 + 0] + v.y * W_lin[(k + 1) * 2 + 0] +
               v.z * W_lin[(k + 2) * 2 + 0] + v.w * W_lin[(k + 3) * 2 + 0];
    float l1 = v.x * W_lin[(k + 0) * 2 + 1] + v.y * W_lin[(k + 1) * 2 + 1] +
               v.z * W_lin[(k + 2) * 2 + 1] + v.w * W_lin[(k + 3) * 2 + 1];

#pragma unroll
    for (int off = 16; off > 0; off >>= 1) {
        l0 += __shfl_xor_sync(0xFFFFFFFFu, l0, off);
        l1 += __shfl_xor_sync(0xFFFFFFFFu, l1, off);
    }

    if (lane == 0) {
        l0 += b_lin[0];
        l1 += b_lin[1];
        float m  = fmaxf(l0, l1);
        float e0 = expf(l0 - m), e1 = expf(l1 - m);
        float s  = e0 + e1;
        out[i * 2 + 0] = e0 / s;
        out[i * 2 + 1] = e1 / s;
    }
}

// -----------------------------------------------------------------------------
extern "C" void kernel_launch(void* const* d_in, const int* in_sizes, int n_in,
                              void* d_out, int out_size) {
    const float* x      = (const float*)d_in[0];
    const void*  ei     = d_in[1];                  // int64 or int32 (detected)
    const float* ew     = (const float*)d_in[2];
    const float* W_conv = (const float*)d_in[3];
    const float* b_conv = (const float*)d_in[4];
    const float* W_lin  = (const float*)d_in[5];
    const float* b_lin  = (const float*)d_in[6];
    float* out = (float*)d_out;

    k_detect<<<1, 32>>>((const long long*)ei);
    k_deg_init<<<(N_NODES + 255) / 256, 256>>>();
    k_deg_accum<<<(N_EDGES + 255) / 256, 256>>>(ei, ew);
    k_dinv<<<(N_NODES + 255) / 256, 256>>>();
    dim3 wg((IN_DIM + 31) / 32, HID / 32);
    k_wsplit<<<wg, 256>>>(W_conv);
    dim3 gg((N_NODES + BM - 1) / BM, HID / BN);
    k_gemm_mma<<<gg, 128>>>(x);
    k_scatter<<<(N_EDGES + 7) / 8, 256>>>(ei, ew);
    k_head<<<(N_NODES + 7) / 8, 256>>>(b_conv, W_lin, b_lin, out);
}

// round 6
// speedup vs baseline: 4.1383x; 1.1033x over previous
#include <cuda_runtime.h>
#include <cuda_bf16.h>
#include <math.h>
#include <stdint.h>

#define N_NODES 10000
#define N_EDGES 320000
#define IN_DIM  10000
#define HID     128
#define NCLS    2

// ---------------- scratch (no allocs allowed) --------------------------------
__device__ float g_h[(size_t)N_NODES * HID];     // x @ W_conv
__device__ float g_agg[(size_t)N_NODES * HID];   // aggregated messages
__device__ float g_deg[N_NODES];
__device__ float g_dinv[N_NODES];
__device__ int   g_is32;                         // edge_index dtype flag
__device__ __nv_bfloat16 g_Wt_hi[(size_t)HID * IN_DIM];  // W^T hi split [128][10000]
__device__ __nv_bfloat16 g_Wt_lo[(size_t)HID * IN_DIM];  // W^T lo split

// ---------------- helpers ----------------------------------------------------
__device__ __forceinline__ uint32_t smem_u32(const void* p) {
    uint32_t a;
    asm("{ .reg .u64 t; cvta.to.shared.u64 t, %1; cvt.u32.u64 %0, t; }"
        : "=r"(a) : "l"(p));
    return a;
}

#define LDSM4(r, addr)                                                         \
    asm volatile("ldmatrix.sync.aligned.m8n8.x4.shared.b16 {%0,%1,%2,%3}, [%4];" \
                 : "=r"((r)[0]), "=r"((r)[1]), "=r"((r)[2]), "=r"((r)[3])      \
                 : "r"(addr))

#define MMA16816(d, a, b0, b1)                                                 \
    asm volatile("mma.sync.aligned.m16n8k16.row.col.f32.bf16.bf16.f32 "        \
                 "{%0,%1,%2,%3}, {%4,%5,%6,%7}, {%8,%9}, {%0,%1,%2,%3};"       \
                 : "+f"((d)[0]), "+f"((d)[1]), "+f"((d)[2]), "+f"((d)[3])      \
                 : "r"((a)[0]), "r"((a)[1]), "r"((a)[2]), "r"((a)[3]),         \
                   "r"(b0), "r"(b1))

// ---------------- init: deg=1 (self loop) + edge dtype detection -------------
__global__ void k_init(const long long* ei) {
    int i = blockIdx.x * blockDim.x + threadIdx.x;
    if (i < N_NODES) g_deg[i] = 1.0f;
    if (i == 0) {
        int is32 = 0;
        for (int j = 0; j < 16; j++) {
            long long v = ei[j];
            if (v < 0 || v >= N_NODES) { is32 = 1; break; }
        }
        g_is32 = is32;
    }
}
__device__ __forceinline__ int edge_idx(const void* ei, long long i) {
    if (g_is32) return ((const int*)ei)[i];
    return (int)((const long long*)ei)[i];
}

__global__ void k_deg_accum(const void* ei, const float* __restrict__ ew) {
    int e = blockIdx.x * blockDim.x + threadIdx.x;
    if (e < N_EDGES) {
        int c = edge_idx(ei, (long long)N_EDGES + e);
        atomicAdd(&g_deg[c], ew[e]);
    }
}
__global__ void k_dinv() {
    int i = blockIdx.x * blockDim.x + threadIdx.x;
    if (i < N_NODES) {
        float d = g_deg[i];
        g_dinv[i] = (d > 0.0f) ? rsqrtf(d) : 0.0f;
    }
}

// ---------------- W transpose + bf16 hi/lo split -----------------------------
__global__ __launch_bounds__(256) void k_wsplit(const float* __restrict__ W) {
    __shared__ float t[32][33];
    int kb = blockIdx.x * 32, nb = blockIdx.y * 32;
    int tx = threadIdx.x & 31, ty = threadIdx.x >> 5;   // ty 0..7
#pragma unroll
    for (int r = ty; r < 32; r += 8) {
        int k = kb + r;
        t[r][tx] = (k < IN_DIM) ? W[(size_t)k * HID + nb + tx] : 0.0f;
    }
    __syncthreads();
#pragma unroll
    for (int r = ty; r < 32; r += 8) {
        int n = nb + r;
        int k = kb + tx;
        if (k < IN_DIM) {
            float v = t[tx][r];
            __nv_bfloat16 hi = __float2bfloat16(v);
            __nv_bfloat16 lo = __float2bfloat16(v - __bfloat162float(hi));
            g_Wt_hi[(size_t)n * IN_DIM + k] = hi;
            g_Wt_lo[(size_t)n * IN_DIM + k] = lo;
        }
    }
}

// ---------------- HMMA GEMM: h = x @ W_conv (bf16x3 split) -------------------
// BM=64, BN=64, BK=32, 128 threads (4 warps in 2x2), warptile 32x32.
// One __syncthreads per K-chunk: stores write buf p^1 (last read two barriers
// ago), compute reads buf p, barrier at end of chunk.
#define BM 64
#define BN 64
#define BK 32
#define STR 40   // padded smem row stride in bf16 elements (80 B)
#define NCH ((IN_DIM + BK - 1) / BK)   // 313

__global__ __launch_bounds__(128) void k_gemm_mma(const float* __restrict__ x) {
    __shared__ __align__(16) __nv_bfloat16 sA[2][2][BM * STR];  // [buf][hi/lo]
    __shared__ __align__(16) __nv_bfloat16 sB[2][2][BN * STR];

    const int tid  = threadIdx.x;
    const int lane = tid & 31;
    const int wid  = tid >> 5;
    const int wm   = wid >> 1;          // 0..1
    const int wn   = wid & 1;           // 0..1
    const int m0   = blockIdx.y * BM;
    const int n0   = blockIdx.x * BN;

    float acc[2][4][4];
#pragma unroll
    for (int a = 0; a < 2; a++)
#pragma unroll
        for (int b = 0; b < 4; b++)
#pragma unroll
            for (int c = 0; c < 4; c++) acc[a][b][c] = 0.0f;

    float4 pa[4];
    uint4  pbh[2], pbl[2];

#define LOADG(cc)                                                              \
    {                                                                          \
        const int k0 = (cc) * BK;                                              \
        _Pragma("unroll")                                                      \
        for (int i = 0; i < 4; i++) {                                          \
            int q = tid + 128 * i, row = q >> 3, c4 = q & 7;                   \
            int gm = m0 + row, k = k0 + c4 * 4;                                \
            pa[i] = (gm < N_NODES && k < IN_DIM)                               \
                        ? *(const float4*)(x + (size_t)gm * IN_DIM + k)        \
                        : make_float4(0.f, 0.f, 0.f, 0.f);                     \
        }                                                                      \
        _Pragma("unroll")                                                      \
        for (int i = 0; i < 2; i++) {                                          \
            int q = tid + 128 * i, row = q >> 2, c4 = q & 3;                   \
            int n = n0 + row, k = k0 + c4 * 8;                                 \
            if (k < IN_DIM) {                                                  \
                pbh[i] = *(const uint4*)(g_Wt_hi + (size_t)n * IN_DIM + k);    \
                pbl[i] = *(const uint4*)(g_Wt_lo + (size_t)n * IN_DIM + k);    \
            } else {                                                           \
                pbh[i] = make_uint4(0, 0, 0, 0);                               \
                pbl[i] = make_uint4(0, 0, 0, 0);                               \
            }                                                                  \
        }                                                                      \
    }

#define STORES(p)                                                              \
    {                                                                          \
        _Pragma("unroll")                                                      \
        for (int i = 0; i < 4; i++) {                                          \
            int q = tid + 128 * i, row = q >> 3, c4 = q & 7;                   \
            float4 v = pa[i];                                                  \
            __nv_bfloat162 h0 = __float22bfloat162_rn(make_float2(v.x, v.y));  \
            __nv_bfloat162 h1 = __float22bfloat162_rn(make_float2(v.z, v.w));  \
            float2 f0 = __bfloat1622float2(h0), f1 = __bfloat1622float2(h1);   \
            __nv_bfloat162 l0 = __float22bfloat162_rn(                         \
                make_float2(v.x - f0.x, v.y - f0.y));                          \
            __nv_bfloat162 l1 = __float22bfloat162_rn(                         \
                make_float2(v.z - f1.x, v.w - f1.y));                          \
            uint2 hh = make_uint2(*(uint32_t*)&h0, *(uint32_t*)&h1);           \
            uint2 ll = make_uint2(*(uint32_t*)&l0, *(uint32_t*)&l1);           \
            *(uint2*)&sA[p][0][row * STR + c4 * 4] = hh;                       \
            *(uint2*)&sA[p][1][row * STR + c4 * 4] = ll;                       \
        }                                                                      \
        _Pragma("unroll")                                                      \
        for (int i = 0; i < 2; i++) {                                          \
            int q = tid + 128 * i, row = q >> 2, c4 = q & 3;                   \
            *(uint4*)&sB[p][0][row * STR + c4 * 8] = pbh[i];                   \
            *(uint4*)&sB[p][1][row * STR + c4 * 8] = pbl[i];                   \
        }                                                                      \
    }

    LOADG(0);
    STORES(0);
    LOADG(1);               // registers now hold chunk 1
    __syncthreads();

    const int lr = lane & 15;
    const int lc = lane >> 4;

    for (int c = 0; c < NCH; c++) {
        const int p = c & 1;
        // stores for chunk c+1 into buf p^1 (free since barrier of iter c-1),
        // then prefetch chunk c+2 into registers, then MMA on buf p.
        if (c + 1 < NCH) STORES((c + 1) & 1);
        if (c + 2 < NCH) LOADG(c + 2);

        const uint32_t aHi = smem_u32(&sA[p][0][0]);
        const uint32_t aLo = smem_u32(&sA[p][1][0]);
        const uint32_t bHi = smem_u32(&sB[p][0][0]);
        const uint32_t bLo = smem_u32(&sB[p][1][0]);
#pragma unroll
        for (int ks = 0; ks < 2; ks++) {
            uint32_t ah[2][4], al[2][4], bh[2][4], bl[2][4];
#pragma unroll
            for (int mi = 0; mi < 2; mi++) {
                uint32_t off = (uint32_t)((wm * 32 + mi * 16 + lr) * STR) * 2 +
                               ks * 32 + lc * 16;
                LDSM4(ah[mi], aHi + off);
                LDSM4(al[mi], aLo + off);
            }
#pragma unroll
            for (int g = 0; g < 2; g++) {
                uint32_t off = (uint32_t)((wn * 32 + g * 16 + lr) * STR) * 2 +
                               ks * 32 + lc * 16;
                LDSM4(bh[g], bHi + off);
                LDSM4(bl[g], bLo + off);
            }
            // term-major ordering: consecutive MMAs hit different accumulators
#pragma unroll
            for (int mi = 0; mi < 2; mi++)
#pragma unroll
                for (int ni = 0; ni < 4; ni++) {
                    int g = ni >> 1, h = ni & 1;
                    MMA16816(acc[mi][ni], ah[mi], bh[g][h], bh[g][h + 2]);
                }
#pragma unroll
            for (int mi = 0; mi < 2; mi++)
#pragma unroll
                for (int ni = 0; ni < 4; ni++) {
                    int g = ni >> 1, h = ni & 1;
                    MMA16816(acc[mi][ni], ah[mi], bl[g][h], bl[g][h + 2]);
                }
#pragma unroll
            for (int mi = 0; mi < 2; mi++)
#pragma unroll
                for (int ni = 0; ni < 4; ni++) {
                    int g = ni >> 1, h = ni & 1;
                    MMA16816(acc[mi][ni], al[mi], bh[g][h], bh[g][h + 2]);
                }
        }
        __syncthreads();
    }

    // epilogue: write g_h and g_agg (self-loop pre-scaled by dinv^2)
#pragma unroll
    for (int mi = 0; mi < 2; mi++) {
#pragma unroll
        for (int half = 0; half < 2; half++) {
            int row = m0 + wm * 32 + mi * 16 + (lane >> 2) + half * 8;
            if (row < N_NODES) {
                float d2 = g_dinv[row];
                d2 *= d2;
#pragma unroll
                for (int ni = 0; ni < 4; ni++) {
                    int col = n0 + wn * 32 + ni * 8 + (lane & 3) * 2;
                    float v0 = acc[mi][ni][2 * half];
                    float v1 = acc[mi][ni][2 * half + 1];
                    size_t o = (size_t)row * HID + col;
                    *(float2*)&g_h[o]   = make_float2(v0, v1);
                    *(float2*)&g_agg[o] = make_float2(d2 * v0, d2 * v1);
                }
            }
        }
    }
#undef LOADG
#undef STORES
}

// ---------------- edge scatter: one warp per edge, vector RED ----------------
__global__ __launch_bounds__(256) void k_scatter(const void* ei,
                                                 const float* __restrict__ ew) {
    int gw   = blockIdx.x * 8 + (threadIdx.x >> 5);
    int lane = threadIdx.x & 31;
    if (gw >= N_EDGES) return;
    int r = edge_idx(ei, gw);                          // row (source)
    int c = edge_idx(ei, (long long)N_EDGES + gw);     // col (dest)
    float w = g_dinv[r] * ew[gw] * g_dinv[c];
    float4 v = ((const float4*)(g_h + (size_t)r * HID))[lane];
    float* ap = g_agg + (size_t)c * HID + lane * 4;
    asm volatile("red.global.add.v4.f32 [%0], {%1, %2, %3, %4};"
                 :: "l"(ap), "f"(w * v.x), "f"(w * v.y), "f"(w * v.z), "f"(w * v.w)
                 : "memory");
}

// ---------------- head: relu(agg + b_conv) @ W_lin + b_lin, softmax ----------
__global__ __launch_bounds__(256) void k_head(const float* __restrict__ b_conv,
                                              const float* __restrict__ W_lin,
                                              const float* __restrict__ b_lin,
                                              float* __restrict__ out) {
    int i    = blockIdx.x * 8 + (threadIdx.x >> 5);
    int lane = threadIdx.x & 31;
    if (i >= N_NODES) return;

    float4 v = ((const float4*)(g_agg + (size_t)i * HID))[lane];
    float4 b = ((const float4*)b_conv)[lane];
    v.x = fmaxf(v.x + b.x, 0.0f);
    v.y = fmaxf(v.y + b.y, 0.0f);
    v.z = fmaxf(v.z + b.z, 0.0f);
    v.w = fmaxf(v.w + b.w, 0.0f);

    int k = lane * 4;
    float l0 = v.x * W_lin[(k + 0) * 2 + 0] + v.y * W_lin[(k + 1) * 2 + 0] +
               v.z * W_lin[(k + 2) * 2 + 0] + v.w * W_lin[(k + 3) * 2 + 0];
    float l1 = v.x * W_lin[(k + 0) * 2 + 1] + v.y * W_lin[(k + 1) * 2 + 1] +
               v.z * W_lin[(k + 2) * 2 + 1] + v.w * W_lin[(k + 3) * 2 + 1];

#pragma unroll
    for (int off = 16; off > 0; off >>= 1) {
        l0 += __shfl_xor_sync(0xFFFFFFFFu, l0, off);
        l1 += __shfl_xor_sync(0xFFFFFFFFu, l1, off);
    }

    if (lane == 0) {
        l0 += b_lin[0];
        l1 += b_lin[1];
        float m  = fmaxf(l0, l1);
        float e0 = expf(l0 - m), e1 = expf(l1 - m);
        float s  = e0 + e1;
        out[i * 2 + 0] = e0 / s;
        out[i * 2 + 1] = e1 / s;
    }
}

// -----------------------------------------------------------------------------
extern "C" void kernel_launch(void* const* d_in, const int* in_sizes, int n_in,
                              void* d_out, int out_size) {
    const float* x      = (const float*)d_in[0];
    const void*  ei     = d_in[1];                  // int64 or int32 (detected)
    const float* ew     = (const float*)d_in[2];
    const float* W_conv = (const float*)d_in[3];
    const float* b_conv = (const float*)d_in[4];
    const float* W_lin  = (const float*)d_in[5];
    const float* b_lin  = (const float*)d_in[6];
    float* out = (float*)d_out;

    k_init<<<(N_NODES + 255) / 256, 256>>>((const long long*)ei);
    k_deg_accum<<<(N_EDGES + 255) / 256, 256>>>(ei, ew);
    k_dinv<<<(N_NODES + 255) / 256, 256>>>();
    dim3 wg((IN_DIM + 31) / 32, HID / 32);
    k_wsplit<<<wg, 256>>>(W_conv);
    dim3 gg(HID / BN, (N_NODES + BM - 1) / BM);   // (2, 157): N-pairs adjacent
    k_gemm_mma<<<gg, 128>>>(x);
    k_scatter<<<(N_EDGES + 7) / 8, 256>>>(ei, ew);
    k_head<<<(N_NODES + 7) / 8, 256>>>(b_conv, W_lin, b_lin, out);
}

// round 7
// speedup vs baseline: 5.2374x; 1.2656x over previous
#include <cuda_runtime.h>
#include <cuda_bf16.h>
#include <math.h>
#include <stdint.h>

#define N_NODES 10000
#define N_EDGES 320000
#define IN_DIM  10000
#define HID     128
#define NCLS    2

// ---------------- scratch (no allocs allowed) --------------------------------
__device__ float g_h[(size_t)N_NODES * HID];     // x @ W_conv (atomic-accumulated)
__device__ float g_agg[(size_t)N_NODES * HID];   // aggregated messages
__device__ float g_deg[N_NODES];
__device__ float g_dinv[N_NODES];
__device__ int   g_is32;                         // edge_index dtype flag
__device__ __nv_bfloat16 g_Wt_hi[(size_t)HID * IN_DIM];  // W^T hi split [128][10000]
__device__ __nv_bfloat16 g_Wt_lo[(size_t)HID * IN_DIM];  // W^T lo split

// ---------------- helpers ----------------------------------------------------
__device__ __forceinline__ uint32_t smem_u32(const void* p) {
    uint32_t a;
    asm("{ .reg .u64 t; cvta.to.shared.u64 t, %1; cvt.u32.u64 %0, t; }"
        : "=r"(a) : "l"(p));
    return a;
}

#define LDSM4(r, addr)                                                         \
    asm volatile("ldmatrix.sync.aligned.m8n8.x4.shared.b16 {%0,%1,%2,%3}, [%4];" \
                 : "=r"((r)[0]), "=r"((r)[1]), "=r"((r)[2]), "=r"((r)[3])      \
                 : "r"(addr))

#define MMA16816(d, a, b0, b1)                                                 \
    asm volatile("mma.sync.aligned.m16n8k16.row.col.f32.bf16.bf16.f32 "        \
                 "{%0,%1,%2,%3}, {%4,%5,%6,%7}, {%8,%9}, {%0,%1,%2,%3};"       \
                 : "+f"((d)[0]), "+f"((d)[1]), "+f"((d)[2]), "+f"((d)[3])      \
                 : "r"((a)[0]), "r"((a)[1]), "r"((a)[2]), "r"((a)[3]),         \
                   "r"(b0), "r"(b1))

// ---------------- init: zero g_h, deg=1, edge dtype detection ----------------
__global__ void k_init(const long long* ei) {
    int i = blockIdx.x * blockDim.x + threadIdx.x;
    if (i < (N_NODES * HID) / 4)
        ((float4*)g_h)[i] = make_float4(0.f, 0.f, 0.f, 0.f);
    if (i < N_NODES) g_deg[i] = 1.0f;
    if (i == 0) {
        int is32 = 0;
        for (int j = 0; j < 16; j++) {
            long long v = ei[j];
            if (v < 0 || v >= N_NODES) { is32 = 1; break; }
        }
        g_is32 = is32;
    }
}
__device__ __forceinline__ int edge_idx(const void* ei, long long i) {
    if (g_is32) return ((const int*)ei)[i];
    return (int)((const long long*)ei)[i];
}

__global__ void k_deg_accum(const void* ei, const float* __restrict__ ew) {
    int e = blockIdx.x * blockDim.x + threadIdx.x;
    if (e < N_EDGES) {
        int c = edge_idx(ei, (long long)N_EDGES + e);
        atomicAdd(&g_deg[c], ew[e]);
    }
}
__global__ void k_dinv() {
    int i = blockIdx.x * blockDim.x + threadIdx.x;
    if (i < N_NODES) {
        float d = g_deg[i];
        g_dinv[i] = (d > 0.0f) ? rsqrtf(d) : 0.0f;
    }
}

// ---------------- W transpose + bf16 hi/lo split -----------------------------
__global__ __launch_bounds__(256) void k_wsplit(const float* __restrict__ W) {
    __shared__ float t[32][33];
    int kb = blockIdx.x * 32, nb = blockIdx.y * 32;
    int tx = threadIdx.x & 31, ty = threadIdx.x >> 5;   // ty 0..7
#pragma unroll
    for (int r = ty; r < 32; r += 8) {
        int k = kb + r;
        t[r][tx] = (k < IN_DIM) ? W[(size_t)k * HID + nb + tx] : 0.0f;
    }
    __syncthreads();
#pragma unroll
    for (int r = ty; r < 32; r += 8) {
        int n = nb + r;
        int k = kb + tx;
        if (k < IN_DIM) {
            float v = t[tx][r];
            __nv_bfloat16 hi = __float2bfloat16(v);
            __nv_bfloat16 lo = __float2bfloat16(v - __bfloat162float(hi));
            g_Wt_hi[(size_t)n * IN_DIM + k] = hi;
            g_Wt_lo[(size_t)n * IN_DIM + k] = lo;
        }
    }
}

// ---------------- HMMA GEMM: h = x @ W_conv (bf16x3 split, K-split x3) -------
// BM=128, BN=128, BK=32; 512 threads = 16 warps in 4x4; warptile 32x32.
// grid = (3 k-splits, 79 m-tiles); partial sums red.global'd into g_h.
#define BM 128
#define BN 128
#define BK 32
#define STR 40                          // padded smem row stride (80 B)
#define NCHT ((IN_DIM + BK - 1) / BK)   // 313 total chunks
#define KSPL 3
#define CPS  ((NCHT + KSPL - 1) / KSPL) // 105 chunks per split
#define ABLK (BM * STR * 2)             // 10240 B per (buf,dt) A block
#define GSMEM (8 * ABLK)                // 81920 B total (4 A blocks + 4 B blocks)

__global__ __launch_bounds__(512, 1) void k_gemm_mma(const float* __restrict__ x) {
    extern __shared__ __align__(16) char smem[];
    // layout: A[buf][dt] at (buf*2+dt)*ABLK; B[buf][dt] at 4*ABLK + (buf*2+dt)*ABLK
#define SAp(buf, dt) ((__nv_bfloat16*)(smem + ((buf) * 2 + (dt)) * ABLK))
#define SBp(buf, dt) ((__nv_bfloat16*)(smem + (4 + (buf) * 2 + (dt)) * ABLK))

    const int tid  = threadIdx.x;
    const int lane = tid & 31;
    const int wid  = tid >> 5;
    const int wm   = wid >> 2;          // 0..3
    const int wn   = wid & 3;           // 0..3
    const int m0   = blockIdx.y * BM;
    const int cs   = blockIdx.x * CPS;
    const int ce   = min(cs + CPS, NCHT);
    const int nch  = ce - cs;

    float acc[2][4][4];
#pragma unroll
    for (int a = 0; a < 2; a++)
#pragma unroll
        for (int b = 0; b < 4; b++)
#pragma unroll
            for (int c = 0; c < 4; c++) acc[a][b][c] = 0.0f;

    float4 pa[2];
    uint4  pbh, pbl;

#define LOADG(cc)                                                              \
    {                                                                          \
        const int k0 = (cc) * BK;                                              \
        _Pragma("unroll")                                                      \
        for (int i = 0; i < 2; i++) {                                          \
            int q = tid + 512 * i, row = q >> 3, c4 = q & 7;                   \
            int gm = m0 + row, k = k0 + c4 * 4;                                \
            pa[i] = (gm < N_NODES && k < IN_DIM)                               \
                        ? *(const float4*)(x + (size_t)gm * IN_DIM + k)        \
                        : make_float4(0.f, 0.f, 0.f, 0.f);                     \
        }                                                                      \
        {                                                                      \
            int row = tid >> 2, c4 = tid & 3;                                  \
            int k = k0 + c4 * 8;                                               \
            if (k < IN_DIM) {                                                  \
                pbh = *(const uint4*)(g_Wt_hi + (size_t)row * IN_DIM + k);     \
                pbl = *(const uint4*)(g_Wt_lo + (size_t)row * IN_DIM + k);     \
            } else {                                                           \
                pbh = make_uint4(0, 0, 0, 0);                                  \
                pbl = make_uint4(0, 0, 0, 0);                                  \
            }                                                                  \
        }                                                                      \
    }

#define STORES(p)                                                              \
    {                                                                          \
        _Pragma("unroll")                                                      \
        for (int i = 0; i < 2; i++) {                                          \
            int q = tid + 512 * i, row = q >> 3, c4 = q & 7;                   \
            float4 v = pa[i];                                                  \
            __nv_bfloat162 h0 = __float22bfloat162_rn(make_float2(v.x, v.y));  \
            __nv_bfloat162 h1 = __float22bfloat162_rn(make_float2(v.z, v.w));  \
            float2 f0 = __bfloat1622float2(h0), f1 = __bfloat1622float2(h1);   \
            __nv_bfloat162 l0 = __float22bfloat162_rn(                         \
                make_float2(v.x - f0.x, v.y - f0.y));                          \
            __nv_bfloat162 l1 = __float22bfloat162_rn(                         \
                make_float2(v.z - f1.x, v.w - f1.y));                          \
            uint2 hh = make_uint2(*(uint32_t*)&h0, *(uint32_t*)&h1);           \
            uint2 ll = make_uint2(*(uint32_t*)&l0, *(uint32_t*)&l1);           \
            *(uint2*)(SAp(p, 0) + row * STR + c4 * 4) = hh;                    \
            *(uint2*)(SAp(p, 1) + row * STR + c4 * 4) = ll;                    \
        }                                                                      \
        {                                                                      \
            int row = tid >> 2, c4 = tid & 3;                                  \
            *(uint4*)(SBp(p, 0) + row * STR + c4 * 8) = pbh;                   \
            *(uint4*)(SBp(p, 1) + row * STR + c4 * 8) = pbl;                   \
        }                                                                      \
    }

    LOADG(cs);
    STORES(0);
    LOADG(cs + 1);          // registers now hold chunk cs+1
    __syncthreads();

    const int lr = lane & 15;
    const int lc = lane >> 4;

    for (int ci = 0; ci < nch; ci++) {
        const int p = ci & 1;
        if (ci + 1 < nch) STORES((ci + 1) & 1);
        if (ci + 2 < nch) LOADG(cs + ci + 2);

        const uint32_t aHi = smem_u32(SAp(p, 0));
        const uint32_t aLo = smem_u32(SAp(p, 1));
        const uint32_t bHi = smem_u32(SBp(p, 0));
        const uint32_t bLo = smem_u32(SBp(p, 1));
#pragma unroll
        for (int ks = 0; ks < 2; ks++) {
            uint32_t ah[2][4], al[2][4], bh[2][4], bl[2][4];
#pragma unroll
            for (int mi = 0; mi < 2; mi++) {
                uint32_t off = (uint32_t)((wm * 32 + mi * 16 + lr) * STR) * 2 +
                               ks * 32 + lc * 16;
                LDSM4(ah[mi], aHi + off);
                LDSM4(al[mi], aLo + off);
            }
#pragma unroll
            for (int g = 0; g < 2; g++) {
                uint32_t off = (uint32_t)((wn * 32 + g * 16 + lr) * STR) * 2 +
                               ks * 32 + lc * 16;
                LDSM4(bh[g], bHi + off);
                LDSM4(bl[g], bLo + off);
            }
            // term-major: consecutive MMAs hit different accumulators
#pragma unroll
            for (int mi = 0; mi < 2; mi++)
#pragma unroll
                for (int ni = 0; ni < 4; ni++) {
                    int g = ni >> 1, h = ni & 1;
                    MMA16816(acc[mi][ni], ah[mi], bh[g][h], bh[g][h + 2]);
                }
#pragma unroll
            for (int mi = 0; mi < 2; mi++)
#pragma unroll
                for (int ni = 0; ni < 4; ni++) {
                    int g = ni >> 1, h = ni & 1;
                    MMA16816(acc[mi][ni], ah[mi], bl[g][h], bl[g][h + 2]);
                }
#pragma unroll
            for (int mi = 0; mi < 2; mi++)
#pragma unroll
                for (int ni = 0; ni < 4; ni++) {
                    int g = ni >> 1, h = ni & 1;
                    MMA16816(acc[mi][ni], al[mi], bh[g][h], bh[g][h + 2]);
                }
        }
        __syncthreads();
    }

    // epilogue: atomic-accumulate partial sums into g_h
#pragma unroll
    for (int mi = 0; mi < 2; mi++) {
#pragma unroll
        for (int half = 0; half < 2; half++) {
            int row = m0 + wm * 32 + mi * 16 + (lane >> 2) + half * 8;
            if (row < N_NODES) {
#pragma unroll
                for (int ni = 0; ni < 4; ni++) {
                    int col = wn * 32 + ni * 8 + (lane & 3) * 2;
                    float v0 = acc[mi][ni][2 * half];
                    float v1 = acc[mi][ni][2 * half + 1];
                    float* hp = g_h + (size_t)row * HID + col;
                    asm volatile("red.global.add.v2.f32 [%0], {%1, %2};"
                                 :: "l"(hp), "f"(v0), "f"(v1) : "memory");
                }
            }
        }
    }
#undef LOADG
#undef STORES
#undef SAp
#undef SBp
}

// ---------------- self-loop: g_agg = dinv^2 * g_h ----------------------------
__global__ void k_selfagg() {
    int i = blockIdx.x * blockDim.x + threadIdx.x;
    if (i < (N_NODES * HID) / 4) {
        int row = i >> 5;               // 32 float4 per row
        float d = g_dinv[row];
        float d2 = d * d;
        float4 v = ((const float4*)g_h)[i];
        ((float4*)g_agg)[i] = make_float4(d2 * v.x, d2 * v.y, d2 * v.z, d2 * v.w);
    }
}

// ---------------- edge scatter: one warp per edge, vector RED ----------------
__global__ __launch_bounds__(256) void k_scatter(const void* ei,
                                                 const float* __restrict__ ew) {
    int gw   = blockIdx.x * 8 + (threadIdx.x >> 5);
    int lane = threadIdx.x & 31;
    if (gw >= N_EDGES) return;
    int r = edge_idx(ei, gw);                          // row (source)
    int c = edge_idx(ei, (long long)N_EDGES + gw);     // col (dest)
    float w = g_dinv[r] * ew[gw] * g_dinv[c];
    float4 v = ((const float4*)(g_h + (size_t)r * HID))[lane];
    float* ap = g_agg + (size_t)c * HID + lane * 4;
    asm volatile("red.global.add.v4.f32 [%0], {%1, %2, %3, %4};"
                 :: "l"(ap), "f"(w * v.x), "f"(w * v.y), "f"(w * v.z), "f"(w * v.w)
                 : "memory");
}

// ---------------- head: relu(agg + b_conv) @ W_lin + b_lin, softmax ----------
__global__ __launch_bounds__(256) void k_head(const float* __restrict__ b_conv,
                                              const float* __restrict__ W_lin,
                                              const float* __restrict__ b_lin,
                                              float* __restrict__ out) {
    int i    = blockIdx.x * 8 + (threadIdx.x >> 5);
    int lane = threadIdx.x & 31;
    if (i >= N_NODES) return;

    float4 v = ((const float4*)(g_agg + (size_t)i * HID))[lane];
    float4 b = ((const float4*)b_conv)[lane];
    v.x = fmaxf(v.x + b.x, 0.0f);
    v.y = fmaxf(v.y + b.y, 0.0f);
    v.z = fmaxf(v.z + b.z, 0.0f);
    v.w = fmaxf(v.w + b.w, 0.0f);

    int k = lane * 4;
    float l0 = v.x * W_lin[(k + 0) * 2 + 0] + v.y * W_lin[(k + 1) * 2 + 0] +
               v.z * W_lin[(k + 2) * 2 + 0] + v.w * W_lin[(k + 3) * 2 + 0];
    float l1 = v.x * W_lin[(k + 0) * 2 + 1] + v.y * W_lin[(k + 1) * 2 + 1] +
               v.z * W_lin[(k + 2) * 2 + 1] + v.w * W_lin[(k + 3) * 2 + 1];

#pragma unroll
    for (int off = 16; off > 0; off >>= 1) {
        l0 += __shfl_xor_sync(0xFFFFFFFFu, l0, off);
        l1 += __shfl_xor_sync(0xFFFFFFFFu, l1, off);
    }

    if (lane == 0) {
        l0 += b_lin[0];
        l1 += b_lin[1];
        float m  = fmaxf(l0, l1);
        float e0 = expf(l0 - m), e1 = expf(l1 - m);
        float s  = e0 + e1;
        out[i * 2 + 0] = e0 / s;
        out[i * 2 + 1] = e1 / s;
    }
}

// -----------------------------------------------------------------------------
extern "C" void kernel_launch(void* const* d_in, const int* in_sizes, int n_in,
                              void* d_out, int out_size) {
    const float* x      = (const float*)d_in[0];
    const void*  ei     = d_in[1];                  // int64 or int32 (detected)
    const float* ew     = (const float*)d_in[2];
    const float* W_conv = (const float*)d_in[3];
    const float* b_conv = (const float*)d_in[4];
    const float* W_lin  = (const float*)d_in[5];
    const float* b_lin  = (const float*)d_in[6];
    float* out = (float*)d_out;

    cudaFuncSetAttribute(k_gemm_mma, cudaFuncAttributeMaxDynamicSharedMemorySize,
                         GSMEM);

    k_init<<<(N_NODES * HID / 4 + 255) / 256, 256>>>((const long long*)ei);
    k_deg_accum<<<(N_EDGES + 255) / 256, 256>>>(ei, ew);
    k_dinv<<<(N_NODES + 255) / 256, 256>>>();
    dim3 wg((IN_DIM + 31) / 32, HID / 32);
    k_wsplit<<<wg, 256>>>(W_conv);
    dim3 gg(KSPL, (N_NODES + BM - 1) / BM);       // (3, 79)
    k_gemm_mma<<<gg, 512, GSMEM>>>(x);
    k_selfagg<<<(N_NODES * HID / 4 + 255) / 256, 256>>>();
    k_scatter<<<(N_EDGES + 7) / 8, 256>>>(ei, ew);
    k_head<<<(N_NODES + 7) / 8, 256>>>(b_conv, W_lin, b_lin, out);
}

// round 8
// speedup vs baseline: 5.9256x; 1.1314x over previous
#include <cuda_runtime.h>
#include <cuda_bf16.h>
#include <math.h>
#include <stdint.h>

#define N_NODES 10000
#define N_EDGES 320000
#define IN_DIM  10000
#define HID     128
#define NCLS    2

// ---------------- scratch (no allocs allowed) --------------------------------
__device__ float g_h[(size_t)N_NODES * HID];     // x @ W_conv (atomic-accumulated)
__device__ float g_agg[(size_t)N_NODES * HID];   // aggregated messages (edges only)
__device__ float g_deg[N_NODES];
__device__ float g_dinv[N_NODES];
__device__ int   g_is32;                         // edge_index dtype flag
__device__ __nv_bfloat16 g_Wt_hi[(size_t)HID * IN_DIM];  // W^T hi split [128][10000]
__device__ __nv_bfloat16 g_Wt_lo[(size_t)HID * IN_DIM];  // W^T lo split

// ---------------- helpers ----------------------------------------------------
__device__ __forceinline__ uint32_t smem_u32(const void* p) {
    uint32_t a;
    asm("{ .reg .u64 t; cvta.to.shared.u64 t, %1; cvt.u32.u64 %0, t; }"
        : "=r"(a) : "l"(p));
    return a;
}

#define LDSM4(r, addr)                                                         \
    asm volatile("ldmatrix.sync.aligned.m8n8.x4.shared.b16 {%0,%1,%2,%3}, [%4];" \
                 : "=r"((r)[0]), "=r"((r)[1]), "=r"((r)[2]), "=r"((r)[3])      \
                 : "r"(addr))

#define MMA16816(d, a, b0, b1)                                                 \
    asm volatile("mma.sync.aligned.m16n8k16.row.col.f32.bf16.bf16.f32 "        \
                 "{%0,%1,%2,%3}, {%4,%5,%6,%7}, {%8,%9}, {%0,%1,%2,%3};"       \
                 : "+f"((d)[0]), "+f"((d)[1]), "+f"((d)[2]), "+f"((d)[3])      \
                 : "r"((a)[0]), "r"((a)[1]), "r"((a)[2]), "r"((a)[3]),         \
                   "r"(b0), "r"(b1))

// ---------------- init: zero g_h + g_agg, deg=1, edge dtype detection --------
__global__ void k_init(const long long* ei) {
    int i = blockIdx.x * blockDim.x + threadIdx.x;
    if (i < (N_NODES * HID) / 4) {
        ((float4*)g_h)[i]   = make_float4(0.f, 0.f, 0.f, 0.f);
        ((float4*)g_agg)[i] = make_float4(0.f, 0.f, 0.f, 0.f);
    }
    if (i < N_NODES) g_deg[i] = 1.0f;
    if (i == 0) {
        int is32 = 0;
        for (int j = 0; j < 16; j++) {
            long long v = ei[j];
            if (v < 0 || v >= N_NODES) { is32 = 1; break; }
        }
        g_is32 = is32;
    }
}
__device__ __forceinline__ int edge_idx(const void* ei, long long i) {
    if (g_is32) return ((const int*)ei)[i];
    return (int)((const long long*)ei)[i];
}

__global__ void k_deg_accum(const void* ei, const float* __restrict__ ew) {
    int e = blockIdx.x * blockDim.x + threadIdx.x;
    if (e < N_EDGES) {
        int c = edge_idx(ei, (long long)N_EDGES + e);
        atomicAdd(&g_deg[c], ew[e]);
    }
}
__global__ void k_dinv() {
    int i = blockIdx.x * blockDim.x + threadIdx.x;
    if (i < N_NODES) {
        float d = g_deg[i];
        g_dinv[i] = (d > 0.0f) ? rsqrtf(d) : 0.0f;
    }
}

// ---------------- W transpose + bf16 hi/lo split -----------------------------
__global__ __launch_bounds__(256) void k_wsplit(const float* __restrict__ W) {
    __shared__ float t[32][33];
    int kb = blockIdx.x * 32, nb = blockIdx.y * 32;
    int tx = threadIdx.x & 31, ty = threadIdx.x >> 5;   // ty 0..7
#pragma unroll
    for (int r = ty; r < 32; r += 8) {
        int k = kb + r;
        t[r][tx] = (k < IN_DIM) ? W[(size_t)k * HID + nb + tx] : 0.0f;
    }
    __syncthreads();
#pragma unroll
    for (int r = ty; r < 32; r += 8) {
        int n = nb + r;
        int k = kb + tx;
        if (k < IN_DIM) {
            float v = t[tx][r];
            __nv_bfloat16 hi = __float2bfloat16(v);
            __nv_bfloat16 lo = __float2bfloat16(v - __bfloat162float(hi));
            g_Wt_hi[(size_t)n * IN_DIM + k] = hi;
            g_Wt_lo[(size_t)n * IN_DIM + k] = lo;
        }
    }
}

// ---------------- HMMA GEMM: h = x @ W_conv (bf16x3 split, K-split x9) -------
// BM=128, BN=128, BK=32; 512 threads = 16 warps in 4x4; warptile 32x32.
// grid = (9 k-splits, 79 m-tiles) = 711 CTAs of ~35 chunks: per-SM load
// quantization 5x35=175 chunk-times vs 2x104=209 at KSPL=3.
#define BM 128
#define BN 128
#define BK 32
#define STR 40                          // padded smem row stride (80 B)
#define NCHT ((IN_DIM + BK - 1) / BK)   // 313 total chunks
#define KSPL 9
#define CPS  ((NCHT + KSPL - 1) / KSPL) // 35 chunks per split (last: 33)
#define ABLK (BM * STR * 2)             // 10240 B per (buf,dt) A block
#define GSMEM (8 * ABLK)                // 81920 B total

__global__ __launch_bounds__(512, 1) void k_gemm_mma(const float* __restrict__ x) {
    extern __shared__ __align__(16) char smem[];
#define SAp(buf, dt) ((__nv_bfloat16*)(smem + ((buf) * 2 + (dt)) * ABLK))
#define SBp(buf, dt) ((__nv_bfloat16*)(smem + (4 + (buf) * 2 + (dt)) * ABLK))

    const int tid  = threadIdx.x;
    const int lane = tid & 31;
    const int wid  = tid >> 5;
    const int wm   = wid >> 2;          // 0..3
    const int wn   = wid & 3;           // 0..3
    const int m0   = blockIdx.y * BM;
    const int cs   = blockIdx.x * CPS;
    const int ce   = min(cs + CPS, NCHT);
    const int nch  = ce - cs;

    float acc[2][4][4];
#pragma unroll
    for (int a = 0; a < 2; a++)
#pragma unroll
        for (int b = 0; b < 4; b++)
#pragma unroll
            for (int c = 0; c < 4; c++) acc[a][b][c] = 0.0f;

    float4 pa[2];
    uint4  pbh, pbl;

#define LOADG(cc)                                                              \
    {                                                                          \
        const int k0 = (cc) * BK;                                              \
        _Pragma("unroll")                                                      \
        for (int i = 0; i < 2; i++) {                                          \
            int q = tid + 512 * i, row = q >> 3, c4 = q & 7;                   \
            int gm = m0 + row, k = k0 + c4 * 4;                                \
            pa[i] = (gm < N_NODES && k < IN_DIM)                               \
                        ? *(const float4*)(x + (size_t)gm * IN_DIM + k)        \
                        : make_float4(0.f, 0.f, 0.f, 0.f);                     \
        }                                                                      \
        {                                                                      \
            int row = tid >> 2, c4 = tid & 3;                                  \
            int k = k0 + c4 * 8;                                               \
            if (k < IN_DIM) {                                                  \
                pbh = *(const uint4*)(g_Wt_hi + (size_t)row * IN_DIM + k);     \
                pbl = *(const uint4*)(g_Wt_lo + (size_t)row * IN_DIM + k);     \
            } else {                                                           \
                pbh = make_uint4(0, 0, 0, 0);                                  \
                pbl = make_uint4(0, 0, 0, 0);                                  \
            }                                                                  \
        }                                                                      \
    }

#define STORES(p)                                                              \
    {                                                                          \
        _Pragma("unroll")                                                      \
        for (int i = 0; i < 2; i++) {                                          \
            int q = tid + 512 * i, row = q >> 3, c4 = q & 7;                   \
            float4 v = pa[i];                                                  \
            __nv_bfloat162 h0 = __float22bfloat162_rn(make_float2(v.x, v.y));  \
            __nv_bfloat162 h1 = __float22bfloat162_rn(make_float2(v.z, v.w));  \
            float2 f0 = __bfloat1622float2(h0), f1 = __bfloat1622float2(h1);   \
            __nv_bfloat162 l0 = __float22bfloat162_rn(                         \
                make_float2(v.x - f0.x, v.y - f0.y));                          \
            __nv_bfloat162 l1 = __float22bfloat162_rn(                         \
                make_float2(v.z - f1.x, v.w - f1.y));                          \
            uint2 hh = make_uint2(*(uint32_t*)&h0, *(uint32_t*)&h1);           \
            uint2 ll = make_uint2(*(uint32_t*)&l0, *(uint32_t*)&l1);           \
            *(uint2*)(SAp(p, 0) + row * STR + c4 * 4) = hh;                    \
            *(uint2*)(SAp(p, 1) + row * STR + c4 * 4) = ll;                    \
        }                                                                      \
        {                                                                      \
            int row = tid >> 2, c4 = tid & 3;                                  \
            *(uint4*)(SBp(p, 0) + row * STR + c4 * 8) = pbh;                   \
            *(uint4*)(SBp(p, 1) + row * STR + c4 * 8) = pbl;                   \
        }                                                                      \
    }

    LOADG(cs);
    STORES(0);
    LOADG(cs + 1);          // registers now hold chunk cs+1
    __syncthreads();

    const int lr = lane & 15;
    const int lc = lane >> 4;

    for (int ci = 0; ci < nch; ci++) {
        const int p = ci & 1;
        if (ci + 1 < nch) STORES((ci + 1) & 1);
        if (ci + 2 < nch) LOADG(cs + ci + 2);

        const uint32_t aHi = smem_u32(SAp(p, 0));
        const uint32_t aLo = smem_u32(SAp(p, 1));
        const uint32_t bHi = smem_u32(SBp(p, 0));
        const uint32_t bLo = smem_u32(SBp(p, 1));
#pragma unroll
        for (int ks = 0; ks < 2; ks++) {
            uint32_t ah[2][4], al[2][4], bh[2][4], bl[2][4];
#pragma unroll
            for (int mi = 0; mi < 2; mi++) {
                uint32_t off = (uint32_t)((wm * 32 + mi * 16 + lr) * STR) * 2 +
                               ks * 32 + lc * 16;
                LDSM4(ah[mi], aHi + off);
                LDSM4(al[mi], aLo + off);
            }
#pragma unroll
            for (int g = 0; g < 2; g++) {
                uint32_t off = (uint32_t)((wn * 32 + g * 16 + lr) * STR) * 2 +
                               ks * 32 + lc * 16;
                LDSM4(bh[g], bHi + off);
                LDSM4(bl[g], bLo + off);
            }
            // term-major: consecutive MMAs hit different accumulators
#pragma unroll
            for (int mi = 0; mi < 2; mi++)
#pragma unroll
                for (int ni = 0; ni < 4; ni++) {
                    int g = ni >> 1, h = ni & 1;
                    MMA16816(acc[mi][ni], ah[mi], bh[g][h], bh[g][h + 2]);
                }
#pragma unroll
            for (int mi = 0; mi < 2; mi++)
#pragma unroll
                for (int ni = 0; ni < 4; ni++) {
                    int g = ni >> 1, h = ni & 1;
                    MMA16816(acc[mi][ni], ah[mi], bl[g][h], bl[g][h + 2]);
                }
#pragma unroll
            for (int mi = 0; mi < 2; mi++)
#pragma unroll
                for (int ni = 0; ni < 4; ni++) {
                    int g = ni >> 1, h = ni & 1;
                    MMA16816(acc[mi][ni], al[mi], bh[g][h], bh[g][h + 2]);
                }
        }
        __syncthreads();
    }

    // epilogue: atomic-accumulate partial sums into g_h
#pragma unroll
    for (int mi = 0; mi < 2; mi++) {
#pragma unroll
        for (int half = 0; half < 2; half++) {
            int row = m0 + wm * 32 + mi * 16 + (lane >> 2) + half * 8;
            if (row < N_NODES) {
#pragma unroll
                for (int ni = 0; ni < 4; ni++) {
                    int col = wn * 32 + ni * 8 + (lane & 3) * 2;
                    float v0 = acc[mi][ni][2 * half];
                    float v1 = acc[mi][ni][2 * half + 1];
                    float* hp = g_h + (size_t)row * HID + col;
                    asm volatile("red.global.add.v2.f32 [%0], {%1, %2};"
                                 :: "l"(hp), "f"(v0), "f"(v1) : "memory");
                }
            }
        }
    }
#undef LOADG
#undef STORES
#undef SAp
#undef SBp
}

// ---------------- edge scatter: one warp per edge, vector RED ----------------
__global__ __launch_bounds__(256) void k_scatter(const void* ei,
                                                 const float* __restrict__ ew) {
    int gw   = blockIdx.x * 8 + (threadIdx.x >> 5);
    int lane = threadIdx.x & 31;
    if (gw >= N_EDGES) return;
    int r = edge_idx(ei, gw);                          // row (source)
    int c = edge_idx(ei, (long long)N_EDGES + gw);     // col (dest)
    float w = g_dinv[r] * ew[gw] * g_dinv[c];
    float4 v = ((const float4*)(g_h + (size_t)r * HID))[lane];
    float* ap = g_agg + (size_t)c * HID + lane * 4;
    asm volatile("red.global.add.v4.f32 [%0], {%1, %2, %3, %4};"
                 :: "l"(ap), "f"(w * v.x), "f"(w * v.y), "f"(w * v.z), "f"(w * v.w)
                 : "memory");
}

// ---------------- head: relu(agg + dinv^2*h + b_conv) @ W_lin, softmax -------
// Self-loop term dinv^2*h[i] is added here (red.add into g_agg is commutative,
// so g_agg holds edge contributions only).
__global__ __launch_bounds__(256) void k_head(const float* __restrict__ b_conv,
                                              const float* __restrict__ W_lin,
                                              const float* __restrict__ b_lin,
                                              float* __restrict__ out) {
    int i    = blockIdx.x * 8 + (threadIdx.x >> 5);
    int lane = threadIdx.x & 31;
    if (i >= N_NODES) return;

    float d2 = g_dinv[i];
    d2 *= d2;
    float4 v  = ((const float4*)(g_agg + (size_t)i * HID))[lane];
    float4 hv = ((const float4*)(g_h   + (size_t)i * HID))[lane];
    float4 b  = ((const float4*)b_conv)[lane];
    v.x = fmaxf(v.x + d2 * hv.x + b.x, 0.0f);
    v.y = fmaxf(v.y + d2 * hv.y + b.y, 0.0f);
    v.z = fmaxf(v.z + d2 * hv.z + b.z, 0.0f);
    v.w = fmaxf(v.w + d2 * hv.w + b.w, 0.0f);

    int k = lane * 4;
    float l0 = v.x * W_lin[(k + 0) * 2 + 0] + v.y * W_lin[(k + 1) * 2 + 0] +
               v.z * W_lin[(k + 2) * 2 + 0] + v.w * W_lin[(k + 3) * 2 + 0];
    float l1 = v.x * W_lin[(k + 0) * 2 + 1] + v.y * W_lin[(k + 1) * 2 + 1] +
               v.z * W_lin[(k + 2) * 2 + 1] + v.w * W_lin[(k + 3) * 2 + 1];

#pragma unroll
    for (int off = 16; off > 0; off >>= 1) {
        l0 += __shfl_xor_sync(0xFFFFFFFFu, l0, off);
        l1 += __shfl_xor_sync(0xFFFFFFFFu, l1, off);
    }

    if (lane == 0) {
        l0 += b_lin[0];
        l1 += b_lin[1];
        float m  = fmaxf(l0, l1);
        float e0 = expf(l0 - m), e1 = expf(l1 - m);
        float s  = e0 + e1;
        out[i * 2 + 0] = e0 / s;
        out[i * 2 + 1] = e1 / s;
    }
}

// -----------------------------------------------------------------------------
extern "C" void kernel_launch(void* const* d_in, const int* in_sizes, int n_in,
                              void* d_out, int out_size) {
    const float* x      = (const float*)d_in[0];
    const void*  ei     = d_in[1];                  // int64 or int32 (detected)
    const float* ew     = (const float*)d_in[2];
    const float* W_conv = (const float*)d_in[3];
    const float* b_conv = (const float*)d_in[4];
    const float* W_lin  = (const float*)d_in[5];
    const float* b_lin  = (const float*)d_in[6];
    float* out = (float*)d_out;

    cudaFuncSetAttribute(k_gemm_mma, cudaFuncAttributeMaxDynamicSharedMemorySize,
                         GSMEM);

    k_init<<<(N_NODES * HID / 4 + 255) / 256, 256>>>((const long long*)ei);
    k_deg_accum<<<(N_EDGES + 255) / 256, 256>>>(ei, ew);
    k_dinv<<<(N_NODES + 255) / 256, 256>>>();
    dim3 wg((IN_DIM + 31) / 32, HID / 32);
    k_wsplit<<<wg, 256>>>(W_conv);
    dim3 gg(KSPL, (N_NODES + BM - 1) / BM);       // (9, 79) = 711 CTAs
    k_gemm_mma<<<gg, 512, GSMEM>>>(x);
    k_scatter<<<(N_EDGES + 7) / 8, 256>>>(ei, ew);
    k_head<<<(N_NODES + 7) / 8, 256>>>(b_conv, W_lin, b_lin, out);
}

// round 10
// speedup vs baseline: 6.3719x; 1.0753x over previous
#include <cuda_runtime.h>
#include <cuda_bf16.h>
#include <math.h>
#include <stdint.h>

#define N_NODES 10000
#define N_EDGES 320000
#define IN_DIM  10000
#define HID     128
#define NCLS    2

// ---------------- scratch (no allocs allowed) --------------------------------
__device__ float g_h[(size_t)N_NODES * HID];     // x @ W_conv (atomic-accumulated)
__device__ float g_agg[(size_t)N_NODES * HID];   // aggregated messages (edges only)
__device__ float g_deg[N_NODES];                 // 1 + sum of incoming edge weights
__device__ int   g_is32;                         // edge_index dtype flag
__device__ __nv_bfloat16 g_Wt_hi[(size_t)HID * IN_DIM];  // W^T hi split [128][10000]
__device__ __nv_bfloat16 g_Wt_lo[(size_t)HID * IN_DIM];  // W^T lo split

// ---------------- helpers ----------------------------------------------------
__device__ __forceinline__ uint32_t smem_u32(const void* p) {
    uint32_t a;
    asm("{ .reg .u64 t; cvta.to.shared.u64 t, %1; cvt.u32.u64 %0, t; }"
        : "=r"(a) : "l"(p));
    return a;
}

#define LDSM4(r, addr)                                                         \
    asm volatile("ldmatrix.sync.aligned.m8n8.x4.shared.b16 {%0,%1,%2,%3}, [%4];" \
                 : "=r"((r)[0]), "=r"((r)[1]), "=r"((r)[2]), "=r"((r)[3])      \
                 : "r"(addr))

#define MMA16816(d, a, b0, b1)                                                 \
    asm volatile("mma.sync.aligned.m16n8k16.row.col.f32.bf16.bf16.f32 "        \
                 "{%0,%1,%2,%3}, {%4,%5,%6,%7}, {%8,%9}, {%0,%1,%2,%3};"       \
                 : "+f"((d)[0]), "+f"((d)[1]), "+f"((d)[2]), "+f"((d)[3])      \
                 : "r"((a)[0]), "r"((a)[1]), "r"((a)[2]), "r"((a)[3]),         \
                   "r"(b0), "r"(b1))

// ---------------- prep: wsplit + zero g_h/g_agg + deg=1 + dtype detect -------
// Blocks [0, 1252): W transpose + bf16 hi/lo split (kb = (bid%313)*32, nb = (bid/313)*32)
// Blocks [1252, 2502): zero g_h/g_agg, seed deg=1, detect edge dtype.
#define WSPLIT_BLOCKS 1252
__global__ __launch_bounds__(256) void k_prep(const float* __restrict__ W,
                                              const long long* ei) {
    __shared__ float t[32][33];
    int bid = blockIdx.x;
    if (bid < WSPLIT_BLOCKS) {
        int kb = (bid % 313) * 32, nb = (bid / 313) * 32;
        int tx = threadIdx.x & 31, ty = threadIdx.x >> 5;   // ty 0..7
#pragma unroll
        for (int r = ty; r < 32; r += 8) {
            int k = kb + r;
            t[r][tx] = (k < IN_DIM) ? W[(size_t)k * HID + nb + tx] : 0.0f;
        }
        __syncthreads();
#pragma unroll
        for (int r = ty; r < 32; r += 8) {
            int n = nb + r;
            int k = kb + tx;
            if (k < IN_DIM) {
                float v = t[tx][r];
                __nv_bfloat16 hi = __float2bfloat16(v);
                __nv_bfloat16 lo = __float2bfloat16(v - __bfloat162float(hi));
                g_Wt_hi[(size_t)n * IN_DIM + k] = hi;
                g_Wt_lo[(size_t)n * IN_DIM + k] = lo;
            }
        }
    } else {
        int i = (bid - WSPLIT_BLOCKS) * 256 + threadIdx.x;
        if (i < (N_NODES * HID) / 4) {
            ((float4*)g_h)[i]   = make_float4(0.f, 0.f, 0.f, 0.f);
            ((float4*)g_agg)[i] = make_float4(0.f, 0.f, 0.f, 0.f);
        }
        if (i < N_NODES) g_deg[i] = 1.0f;   // self-loop weight
        if (i == 0) {
            int is32 = 0;
            for (int j = 0; j < 16; j++) {
                long long v = ei[j];
                if (v < 0 || v >= N_NODES) { is32 = 1; break; }
            }
            g_is32 = is32;
        }
    }
}
__device__ __forceinline__ int edge_idx(const void* ei, long long i) {
    if (g_is32) return ((const int*)ei)[i];
    return (int)((const long long*)ei)[i];
}

__global__ void k_deg_accum(const void* ei, const float* __restrict__ ew) {
    int e = blockIdx.x * blockDim.x + threadIdx.x;
    if (e < N_EDGES) {
        int c = edge_idx(ei, (long long)N_EDGES + e);
        atomicAdd(&g_deg[c], ew[e]);
    }
}

// ---------------- HMMA GEMM: h = x @ W_conv (bf16x3 split, K-split x9) -------
// BM=128, BN=128, BK=32; 512 threads = 16 warps in 4x4; warptile 32x32.
// Feed (A convert+STS, B cp.async, A LDG prefetch) sits between the two
// ks MMA blocks so tensor work starts immediately after each barrier.
#define BM 128
#define BN 128
#define BK 32
#define STR 40                          // padded smem row stride (80 B)
#define NCHT ((IN_DIM + BK - 1) / BK)   // 313 total chunks
#define KSPL 9
#define CPS  ((NCHT + KSPL - 1) / KSPL) // 35 chunks per split (last: 33)
#define ABLK (BM * STR * 2)             // 10240 B per (buf,dt) block
#define GSMEM (8 * ABLK)                // 81920 B total

__global__ __launch_bounds__(512, 1) void k_gemm_mma(const float* __restrict__ x) {
    extern __shared__ __align__(16) char smem[];
#define SAp(buf, dt) ((__nv_bfloat16*)(smem + ((buf) * 2 + (dt)) * ABLK))
#define SBp(buf, dt) ((__nv_bfloat16*)(smem + (4 + (buf) * 2 + (dt)) * ABLK))

    const int tid  = threadIdx.x;
    const int lane = tid & 31;
    const int wid  = tid >> 5;
    const int wm   = wid >> 2;          // 0..3
    const int wn   = wid & 3;           // 0..3
    const int m0   = blockIdx.y * BM;
    const int cs   = blockIdx.x * CPS;
    const int ce   = min(cs + CPS, NCHT);
    const int nch  = ce - cs;

    float acc[2][4][4];
#pragma unroll
    for (int a = 0; a < 2; a++)
#pragma unroll
        for (int b = 0; b < 4; b++)
#pragma unroll
            for (int c = 0; c < 4; c++) acc[a][b][c] = 0.0f;

    float4 pa[2];

#define LOADGA(cc)                                                             \
    {                                                                          \
        const int k0 = (cc) * BK;                                              \
        _Pragma("unroll")                                                      \
        for (int i = 0; i < 2; i++) {                                          \
            int q = tid + 512 * i, row = q >> 3, c4 = q & 7;                   \
            int gm = m0 + row, k = k0 + c4 * 4;                                \
            pa[i] = (gm < N_NODES && k < IN_DIM)                               \
                        ? *(const float4*)(x + (size_t)gm * IN_DIM + k)        \
                        : make_float4(0.f, 0.f, 0.f, 0.f);                     \
        }                                                                      \
    }

#define STORESA(p)                                                             \
    {                                                                          \
        _Pragma("unroll")                                                      \
        for (int i = 0; i < 2; i++) {                                          \
            int q = tid + 512 * i, row = q >> 3, c4 = q & 7;                   \
            float4 v = pa[i];                                                  \
            __nv_bfloat162 h0 = __float22bfloat162_rn(make_float2(v.x, v.y));  \
            __nv_bfloat162 h1 = __float22bfloat162_rn(make_float2(v.z, v.w));  \
            float2 f0 = __bfloat1622float2(h0), f1 = __bfloat1622float2(h1);   \
            __nv_bfloat162 l0 = __float22bfloat162_rn(                         \
                make_float2(v.x - f0.x, v.y - f0.y));                          \
            __nv_bfloat162 l1 = __float22bfloat162_rn(                         \
                make_float2(v.z - f1.x, v.w - f1.y));                          \
            uint2 hh = make_uint2(*(uint32_t*)&h0, *(uint32_t*)&h1);           \
            uint2 ll = make_uint2(*(uint32_t*)&l0, *(uint32_t*)&l1);           \
            *(uint2*)(SAp(p, 0) + row * STR + c4 * 4) = hh;                    \
            *(uint2*)(SAp(p, 1) + row * STR + c4 * 4) = ll;                    \
        }                                                                      \
    }

#define CPB(p, cc)                                                             \
    {                                                                          \
        int row = tid >> 2, c4 = tid & 3;                                      \
        int k = (cc) * BK + c4 * 8;                                            \
        if (k + 8 <= IN_DIM) {                                                 \
            uint32_t dh = smem_u32(SBp(p, 0) + row * STR + c4 * 8);            \
            uint32_t dl = smem_u32(SBp(p, 1) + row * STR + c4 * 8);            \
            const void* sh = g_Wt_hi + (size_t)row * IN_DIM + k;               \
            const void* sl = g_Wt_lo + (size_t)row * IN_DIM + k;               \
            asm volatile("cp.async.ca.shared.global [%0], [%1], 16;"           \
                         :: "r"(dh), "l"(sh));                                 \
            asm volatile("cp.async.ca.shared.global [%0], [%1], 16;"           \
                         :: "r"(dl), "l"(sl));                                 \
        } else {                                                               \
            uint4 z = make_uint4(0, 0, 0, 0);                                  \
            *(uint4*)(SBp(p, 0) + row * STR + c4 * 8) = z;                     \
            *(uint4*)(SBp(p, 1) + row * STR + c4 * 8) = z;                     \
        }                                                                      \
        asm volatile("cp.async.commit_group;");                                \
    }

#define FRAGS(ks)                                                              \
    {                                                                          \
        _Pragma("unroll")                                                      \
        for (int mi = 0; mi < 2; mi++) {                                       \
            uint32_t off = (uint32_t)((wm * 32 + mi * 16 + lr) * STR) * 2 +    \
                           (ks) * 32 + lc * 16;                                \
            LDSM4(ah[mi], aHi + off);                                          \
            LDSM4(al[mi], aLo + off);                                          \
        }                                                                      \
        _Pragma("unroll")                                                      \
        for (int g = 0; g < 2; g++) {                                          \
            uint32_t off = (uint32_t)((wn * 32 + g * 16 + lr) * STR) * 2 +     \
                           (ks) * 32 + lc * 16;                                \
            LDSM4(bh[g], bHi + off);                                           \
            LDSM4(bl[g], bLo + off);                                           \
        }                                                                      \
    }

#define MMAS()                                                                 \
    {                                                                          \
        _Pragma("unroll")                                                      \
        for (int mi = 0; mi < 2; mi++)                                         \
            _Pragma("unroll")                                                  \
            for (int ni = 0; ni < 4; ni++) {                                   \
                int g = ni >> 1, h = ni & 1;                                   \
                MMA16816(acc[mi][ni], ah[mi], bh[g][h], bh[g][h + 2]);         \
            }                                                                  \
        _Pragma("unroll")                                                      \
        for (int mi = 0; mi < 2; mi++)                                         \
            _Pragma("unroll")                                                  \
            for (int ni = 0; ni < 4; ni++) {                                   \
                int g = ni >> 1, h = ni & 1;                                   \
                MMA16816(acc[mi][ni], ah[mi], bl[g][h], bl[g][h + 2]);         \
            }                                                                  \
        _Pragma("unroll")                                                      \
        for (int mi = 0; mi < 2; mi++)                                         \
            _Pragma("unroll")                                                  \
            for (int ni = 0; ni < 4; ni++) {                                   \
                int g = ni >> 1, h = ni & 1;                                   \
                MMA16816(acc[mi][ni], al[mi], bh[g][h], bh[g][h + 2]);         \
            }                                                                  \
    }

    // prologue: fill buf 0 with chunk cs; prefetch chunk cs+1 into registers
    LOADGA(cs);
    STORESA(0);
    CPB(0, cs);
    LOADGA(cs + 1);
    asm volatile("cp.async.wait_group 0;" ::: "memory");
    __syncthreads();

    const int lr = lane & 15;
    const int lc = lane >> 4;

    for (int ci = 0; ci < nch; ci++) {
        const int p = ci & 1;
        const uint32_t aHi = smem_u32(SAp(p, 0));
        const uint32_t aLo = smem_u32(SAp(p, 1));
        const uint32_t bHi = smem_u32(SBp(p, 0));
        const uint32_t bLo = smem_u32(SBp(p, 1));

        uint32_t ah[2][4], al[2][4], bh[2][4], bl[2][4];

        // ks=0: tensor work starts immediately after the barrier
        FRAGS(0);
        MMAS();

        // feed phase (overlaps with other warps' MMAs)
        if (ci + 1 < nch) { STORESA((ci + 1) & 1); CPB((ci + 1) & 1, cs + ci + 1); }
        if (ci + 2 < nch) LOADGA(cs + ci + 2);

        // ks=1
        FRAGS(1);
        MMAS();

        asm volatile("cp.async.wait_group 0;" ::: "memory");
        __syncthreads();
    }

    // epilogue: atomic-accumulate partial sums into g_h
#pragma unroll
    for (int mi = 0; mi < 2; mi++) {
#pragma unroll
        for (int half = 0; half < 2; half++) {
            int row = m0 + wm * 32 + mi * 16 + (lane >> 2) + half * 8;
            if (row < N_NODES) {
#pragma unroll
                for (int ni = 0; ni < 4; ni++) {
                    int col = wn * 32 + ni * 8 + (lane & 3) * 2;
                    float v0 = acc[mi][ni][2 * half];
                    float v1 = acc[mi][ni][2 * half + 1];
                    float* hp = g_h + (size_t)row * HID + col;
                    asm volatile("red.global.add.v2.f32 [%0], {%1, %2};"
                                 :: "l"(hp), "f"(v0), "f"(v1) : "memory");
                }
            }
        }
    }
#undef LOADGA
#undef STORESA
#undef CPB
#undef FRAGS
#undef MMAS
#undef SAp
#undef SBp
}

// ---------------- edge scatter: one warp per edge, vector RED ----------------
__global__ __launch_bounds__(256) void k_scatter(const void* ei,
                                                 const float* __restrict__ ew) {
    int gw   = blockIdx.x * 8 + (threadIdx.x >> 5);
    int lane = threadIdx.x & 31;
    if (gw >= N_EDGES) return;
    int r = edge_idx(ei, gw);                          // row (source)
    int c = edge_idx(ei, (long long)N_EDGES + gw);     // col (dest)
    float w = rsqrtf(g_deg[r]) * ew[gw] * rsqrtf(g_deg[c]);
    float4 v = ((const float4*)(g_h + (size_t)r * HID))[lane];
    float* ap = g_agg + (size_t)c * HID + lane * 4;
    asm volatile("red.global.add.v4.f32 [%0], {%1, %2, %3, %4};"
                 :: "l"(ap), "f"(w * v.x), "f"(w * v.y), "f"(w * v.z), "f"(w * v.w)
                 : "memory");
}

// ---------------- head: relu(agg + dinv^2*h + b_conv) @ W_lin, softmax -------
__global__ __launch_bounds__(256) void k_head(const float* __restrict__ b_conv,
                                              const float* __restrict__ W_lin,
                                              const float* __restrict__ b_lin,
                                              float* __restrict__ out) {
    int i    = blockIdx.x * 8 + (threadIdx.x >> 5);
    int lane = threadIdx.x & 31;
    if (i >= N_NODES) return;

    float dr = rsqrtf(g_deg[i]);
    float d2 = dr * dr;
    float4 v  = ((const float4*)(g_agg + (size_t)i * HID))[lane];
    float4 hv = ((const float4*)(g_h   + (size_t)i * HID))[lane];
    float4 b  = ((const float4*)b_conv)[lane];
    v.x = fmaxf(v.x + d2 * hv.x + b.x, 0.0f);
    v.y = fmaxf(v.y + d2 * hv.y + b.y, 0.0f);
    v.z = fmaxf(v.z + d2 * hv.z + b.z, 0.0f);
    v.w = fmaxf(v.w + d2 * hv.w + b.w, 0.0f);

    int k = lane * 4;
    float l0 = v.x * W_lin[(k + 0) * 2 + 0] + v.y * W_lin[(k + 1) * 2 + 0] +
               v.z * W_lin[(k + 2) * 2 + 0] + v.w * W_lin[(k + 3) * 2 + 0];
    float l1 = v.x * W_lin[(k + 0) * 2 + 1] + v.y * W_lin[(k + 1) * 2 + 1] +
               v.z * W_lin[(k + 2) * 2 + 1] + v.w * W_lin[(k + 3) * 2 + 1];

#pragma unroll
    for (int off = 16; off > 0; off >>= 1) {
        l0 += __shfl_xor_sync(0xFFFFFFFFu, l0, off);
        l1 += __shfl_xor_sync(0xFFFFFFFFu, l1, off);
    }

    if (lane == 0) {
        l0 += b_lin[0];
        l1 += b_lin[1];
        float m  = fmaxf(l0, l1);
        float e0 = expf(l0 - m), e1 = expf(l1 - m);
        float s  = e0 + e1;
        out[i * 2 + 0] = e0 / s;
        out[i * 2 + 1] = e1 / s;
    }
}

// -----------------------------------------------------------------------------
extern "C" void kernel_launch(void* const* d_in, const int* in_sizes, int n_in,
                              void* d_out, int out_size) {
    const float* x      = (const float*)d_in[0];
    const void*  ei     = d_in[1];                  // int64 or int32 (detected)
    const float* ew     = (const float*)d_in[2];
    const float* W_conv = (const float*)d_in[3];
    const float* b_conv = (const float*)d_in[4];
    const float* W_lin  = (const float*)d_in[5];
    const float* b_lin  = (const float*)d_in[6];
    float* out = (float*)d_out;

    cudaFuncSetAttribute(k_gemm_mma, cudaFuncAttributeMaxDynamicSharedMemorySize,
                         GSMEM);

    k_prep<<<WSPLIT_BLOCKS + 1250, 256>>>(W_conv, (const long long*)ei);
    k_deg_accum<<<(N_EDGES + 255) / 256, 256>>>(ei, ew);
    dim3 gg(KSPL, (N_NODES + BM - 1) / BM);       // (9, 79) = 711 CTAs
    k_gemm_mma<<<gg, 512, GSMEM>>>(x);
    k_scatter<<<(N_EDGES + 7) / 8, 256>>>(ei, ew);
    k_head<<<(N_NODES + 7) / 8, 256>>>(b_conv, W_lin, b_lin, out);
}

// round 11
// speedup vs baseline: 6.3847x; 1.0020x over previous
#include <cuda_runtime.h>
#include <cuda_bf16.h>
#include <math.h>
#include <stdint.h>

#define N_NODES 10000
#define N_EDGES 320000
#define IN_DIM  10000
#define HID     128
#define NCLS    2

// ---------------- scratch (no allocs allowed) --------------------------------
__device__ float g_h[(size_t)N_NODES * HID];     // x @ W_conv (atomic-accumulated)
__device__ float g_agg[(size_t)N_NODES * HID];   // aggregated messages (edges only)
__device__ float g_deg[N_NODES];                 // 1 + sum of incoming edge weights
__device__ int   g_is32;                         // edge_index dtype flag
__device__ __nv_bfloat16 g_Wt_hi[(size_t)HID * IN_DIM];  // W^T hi split [128][10000]
__device__ __nv_bfloat16 g_Wt_lo[(size_t)HID * IN_DIM];  // W^T lo split

// ---------------- helpers ----------------------------------------------------
__device__ __forceinline__ uint32_t smem_u32(const void* p) {
    uint32_t a;
    asm("{ .reg .u64 t; cvta.to.shared.u64 t, %1; cvt.u32.u64 %0, t; }"
        : "=r"(a) : "l"(p));
    return a;
}

#define LDSM4(r, addr)                                                         \
    asm volatile("ldmatrix.sync.aligned.m8n8.x4.shared.b16 {%0,%1,%2,%3}, [%4];" \
                 : "=r"((r)[0]), "=r"((r)[1]), "=r"((r)[2]), "=r"((r)[3])      \
                 : "r"(addr))

#define MMA16816(d, a, b0, b1)                                                 \
    asm volatile("mma.sync.aligned.m16n8k16.row.col.f32.bf16.bf16.f32 "        \
                 "{%0,%1,%2,%3}, {%4,%5,%6,%7}, {%8,%9}, {%0,%1,%2,%3};"       \
                 : "+f"((d)[0]), "+f"((d)[1]), "+f"((d)[2]), "+f"((d)[3])      \
                 : "r"((a)[0]), "r"((a)[1]), "r"((a)[2]), "r"((a)[3]),         \
                   "r"(b0), "r"(b1))

// ---------------- prep: wsplit + zero g_h/g_agg + deg=1 + dtype detect -------
#define WSPLIT_BLOCKS 1252
__global__ __launch_bounds__(256) void k_prep(const float* __restrict__ W,
                                              const long long* ei) {
    __shared__ float t[32][33];
    int bid = blockIdx.x;
    if (bid < WSPLIT_BLOCKS) {
        int kb = (bid % 313) * 32, nb = (bid / 313) * 32;
        int tx = threadIdx.x & 31, ty = threadIdx.x >> 5;   // ty 0..7
#pragma unroll
        for (int r = ty; r < 32; r += 8) {
            int k = kb + r;
            t[r][tx] = (k < IN_DIM) ? W[(size_t)k * HID + nb + tx] : 0.0f;
        }
        __syncthreads();
#pragma unroll
        for (int r = ty; r < 32; r += 8) {
            int n = nb + r;
            int k = kb + tx;
            if (k < IN_DIM) {
                float v = t[tx][r];
                __nv_bfloat16 hi = __float2bfloat16(v);
                __nv_bfloat16 lo = __float2bfloat16(v - __bfloat162float(hi));
                g_Wt_hi[(size_t)n * IN_DIM + k] = hi;
                g_Wt_lo[(size_t)n * IN_DIM + k] = lo;
            }
        }
    } else {
        int i = (bid - WSPLIT_BLOCKS) * 256 + threadIdx.x;
        if (i < (N_NODES * HID) / 4) {
            ((float4*)g_h)[i]   = make_float4(0.f, 0.f, 0.f, 0.f);
            ((float4*)g_agg)[i] = make_float4(0.f, 0.f, 0.f, 0.f);
        }
        if (i < N_NODES) g_deg[i] = 1.0f;   // self-loop weight
        if (i == 0) {
            int is32 = 0;
            for (int j = 0; j < 16; j++) {
                long long v = ei[j];
                if (v < 0 || v >= N_NODES) { is32 = 1; break; }
            }
            g_is32 = is32;
        }
    }
}
__device__ __forceinline__ int edge_idx(const void* ei, long long i) {
    if (g_is32) return ((const int*)ei)[i];
    return (int)((const long long*)ei)[i];
}

__global__ void k_deg_accum(const void* ei, const float* __restrict__ ew) {
    int e = blockIdx.x * blockDim.x + threadIdx.x;
    if (e < N_EDGES) {
        int c = edge_idx(ei, (long long)N_EDGES + e);
        atomicAdd(&g_deg[c], ew[e]);
    }
}

// ---------------- HMMA GEMM: h = x @ W_conv (bf16x3 split, K-split x9) -------
// BM=128, BN=128, BK=64; 512 threads = 16 warps in 4x4; warptile 32x32.
// BK=64 halves per-chunk barrier/loop overhead (18 barriers/CTA vs 35).
// Feed sits mid-chunk (between ks=1 and ks=2) for cp.async landing time.
#define BM 128
#define BN 128
#define BK 64
#define STR 72                          // padded smem row stride (144 B)
#define NCHT ((IN_DIM + BK - 1) / BK)   // 157 total chunks
#define KSPL 9
#define CPS  ((NCHT + KSPL - 1) / KSPL) // 18 chunks per split (last: 13)
#define ABLK (BM * STR * 2)             // 18432 B per (buf,dt) block
#define GSMEM (8 * ABLK)                // 147456 B total

__global__ __launch_bounds__(512, 1) void k_gemm_mma(const float* __restrict__ x) {
    extern __shared__ __align__(16) char smem[];
#define SAp(buf, dt) ((__nv_bfloat16*)(smem + ((buf) * 2 + (dt)) * ABLK))
#define SBp(buf, dt) ((__nv_bfloat16*)(smem + (4 + (buf) * 2 + (dt)) * ABLK))

    const int tid  = threadIdx.x;
    const int lane = tid & 31;
    const int wid  = tid >> 5;
    const int wm   = wid >> 2;          // 0..3
    const int wn   = wid & 3;           // 0..3
    const int m0   = blockIdx.y * BM;
    const int cs   = blockIdx.x * CPS;
    const int ce   = min(cs + CPS, NCHT);
    const int nch  = ce - cs;

    float acc[2][4][4];
#pragma unroll
    for (int a = 0; a < 2; a++)
#pragma unroll
        for (int b = 0; b < 4; b++)
#pragma unroll
            for (int c = 0; c < 4; c++) acc[a][b][c] = 0.0f;

    float4 pa[4];

// A tile: 128 rows x 64 floats; 512 threads x 4 iters, 16 float4 per row.
#define LOADGA(cc)                                                             \
    {                                                                          \
        const int k0 = (cc) * BK;                                              \
        _Pragma("unroll")                                                      \
        for (int i = 0; i < 4; i++) {                                          \
            int q = tid + 512 * i, row = q >> 4, c4 = q & 15;                  \
            int gm = m0 + row, k = k0 + c4 * 4;                                \
            pa[i] = (gm < N_NODES && k < IN_DIM)                               \
                        ? *(const float4*)(x + (size_t)gm * IN_DIM + k)        \
                        : make_float4(0.f, 0.f, 0.f, 0.f);                     \
        }                                                                      \
    }

#define STORESA(p)                                                             \
    {                                                                          \
        _Pragma("unroll")                                                      \
        for (int i = 0; i < 4; i++) {                                          \
            int q = tid + 512 * i, row = q >> 4, c4 = q & 15;                  \
            float4 v = pa[i];                                                  \
            __nv_bfloat162 h0 = __float22bfloat162_rn(make_float2(v.x, v.y));  \
            __nv_bfloat162 h1 = __float22bfloat162_rn(make_float2(v.z, v.w));  \
            float2 f0 = __bfloat1622float2(h0), f1 = __bfloat1622float2(h1);   \
            __nv_bfloat162 l0 = __float22bfloat162_rn(                         \
                make_float2(v.x - f0.x, v.y - f0.y));                          \
            __nv_bfloat162 l1 = __float22bfloat162_rn(                         \
                make_float2(v.z - f1.x, v.w - f1.y));                          \
            uint2 hh = make_uint2(*(uint32_t*)&h0, *(uint32_t*)&h1);           \
            uint2 ll = make_uint2(*(uint32_t*)&l0, *(uint32_t*)&l1);           \
            *(uint2*)(SAp(p, 0) + row * STR + c4 * 4) = hh;                    \
            *(uint2*)(SAp(p, 1) + row * STR + c4 * 4) = ll;                    \
        }                                                                      \
    }

// B tile: 128 rows x 64 bf16 per dt; per thread 2 groups of 8 cols, 2 dts.
#define CPB(p, cc)                                                             \
    {                                                                          \
        int row = tid >> 2, c4 = tid & 3;                                      \
        _Pragma("unroll")                                                      \
        for (int g2 = 0; g2 < 2; g2++) {                                       \
            int grp = c4 + g2 * 4;                                             \
            int k = (cc) * BK + grp * 8;                                       \
            if (k + 8 <= IN_DIM) {                                             \
                uint32_t dh = smem_u32(SBp(p, 0) + row * STR + grp * 8);       \
                uint32_t dl = smem_u32(SBp(p, 1) + row * STR + grp * 8);       \
                const void* sh = g_Wt_hi + (size_t)row * IN_DIM + k;           \
                const void* sl = g_Wt_lo + (size_t)row * IN_DIM + k;           \
                asm volatile("cp.async.ca.shared.global [%0], [%1], 16;"       \
                             :: "r"(dh), "l"(sh));                             \
                asm volatile("cp.async.ca.shared.global [%0], [%1], 16;"       \
                             :: "r"(dl), "l"(sl));                             \
            } else {                                                           \
                uint4 z = make_uint4(0, 0, 0, 0);                              \
                *(uint4*)(SBp(p, 0) + row * STR + grp * 8) = z;                \
                *(uint4*)(SBp(p, 1) + row * STR + grp * 8) = z;                \
            }                                                                  \
        }                                                                      \
        asm volatile("cp.async.commit_group;");                                \
    }

#define FRAGS(ks)                                                              \
    {                                                                          \
        _Pragma("unroll")                                                      \
        for (int mi = 0; mi < 2; mi++) {                                       \
            uint32_t off = (uint32_t)((wm * 32 + mi * 16 + lr) * STR) * 2 +    \
                           (ks) * 32 + lc * 16;                                \
            LDSM4(ah[mi], aHi + off);                                          \
            LDSM4(al[mi], aLo + off);                                          \
        }                                                                      \
        _Pragma("unroll")                                                      \
        for (int g = 0; g < 2; g++) {                                          \
            uint32_t off = (uint32_t)((wn * 32 + g * 16 + lr) * STR) * 2 +     \
                           (ks) * 32 + lc * 16;                                \
            LDSM4(bh[g], bHi + off);                                           \
            LDSM4(bl[g], bLo + off);                                           \
        }                                                                      \
    }

#define MMAS()                                                                 \
    {                                                                          \
        _Pragma("unroll")                                                      \
        for (int mi = 0; mi < 2; mi++)                                         \
            _Pragma("unroll")                                                  \
            for (int ni = 0; ni < 4; ni++) {                                   \
                int g = ni >> 1, h = ni & 1;                                   \
                MMA16816(acc[mi][ni], ah[mi], bh[g][h], bh[g][h + 2]);         \
            }                                                                  \
        _Pragma("unroll")                                                      \
        for (int mi = 0; mi < 2; mi++)                                         \
            _Pragma("unroll")                                                  \
            for (int ni = 0; ni < 4; ni++) {                                   \
                int g = ni >> 1, h = ni & 1;                                   \
                MMA16816(acc[mi][ni], ah[mi], bl[g][h], bl[g][h + 2]);         \
            }                                                                  \
        _Pragma("unroll")                                                      \
        for (int mi = 0; mi < 2; mi++)                                         \
            _Pragma("unroll")                                                  \
            for (int ni = 0; ni < 4; ni++) {                                   \
                int g = ni >> 1, h = ni & 1;                                   \
                MMA16816(acc[mi][ni], al[mi], bh[g][h], bh[g][h + 2]);         \
            }                                                                  \
    }

    // prologue: fill buf 0 with chunk cs; prefetch chunk cs+1 into registers
    LOADGA(cs);
    STORESA(0);
    CPB(0, cs);
    LOADGA(cs + 1);
    asm volatile("cp.async.wait_group 0;" ::: "memory");
    __syncthreads();

    const int lr = lane & 15;
    const int lc = lane >> 4;

    for (int ci = 0; ci < nch; ci++) {
        const int p = ci & 1;
        const uint32_t aHi = smem_u32(SAp(p, 0));
        const uint32_t aLo = smem_u32(SAp(p, 1));
        const uint32_t bHi = smem_u32(SBp(p, 0));
        const uint32_t bLo = smem_u32(SBp(p, 1));

        uint32_t ah[2][4], al[2][4], bh[2][4], bl[2][4];

        // first half of the chunk: tensor work starts right after the barrier
        FRAGS(0);
        MMAS();
        FRAGS(1);
        MMAS();

        // mid-chunk feed (prefetch for chunk ci+1 overlaps remaining MMAs)
        if (ci + 1 < nch) { STORESA((ci + 1) & 1); CPB((ci + 1) & 1, cs + ci + 1); }
        if (ci + 2 < nch) LOADGA(cs + ci + 2);

        // second half
        FRAGS(2);
        MMAS();
        FRAGS(3);
        MMAS();

        asm volatile("cp.async.wait_group 0;" ::: "memory");
        __syncthreads();
    }

    // epilogue: atomic-accumulate partial sums into g_h
#pragma unroll
    for (int mi = 0; mi < 2; mi++) {
#pragma unroll
        for (int half = 0; half < 2; half++) {
            int row = m0 + wm * 32 + mi * 16 + (lane >> 2) + half * 8;
            if (row < N_NODES) {
#pragma unroll
                for (int ni = 0; ni < 4; ni++) {
                    int col = wn * 32 + ni * 8 + (lane & 3) * 2;
                    float v0 = acc[mi][ni][2 * half];
                    float v1 = acc[mi][ni][2 * half + 1];
                    float* hp = g_h + (size_t)row * HID + col;
                    asm volatile("red.global.add.v2.f32 [%0], {%1, %2};"
                                 :: "l"(hp), "f"(v0), "f"(v1) : "memory");
                }
            }
        }
    }
#undef LOADGA
#undef STORESA
#undef CPB
#undef FRAGS
#undef MMAS
#undef SAp
#undef SBp
}

// ---------------- edge scatter: one warp per edge, vector RED ----------------
__global__ __launch_bounds__(256) void k_scatter(const void* ei,
                                                 const float* __restrict__ ew) {
    int gw   = blockIdx.x * 8 + (threadIdx.x >> 5);
    int lane = threadIdx.x & 31;
    if (gw >= N_EDGES) return;
    int r = edge_idx(ei, gw);                          // row (source)
    int c = edge_idx(ei, (long long)N_EDGES + gw);     // col (dest)
    float w = rsqrtf(g_deg[r]) * ew[gw] * rsqrtf(g_deg[c]);
    float4 v = ((const float4*)(g_h + (size_t)r * HID))[lane];
    float* ap = g_agg + (size_t)c * HID + lane * 4;
    asm volatile("red.global.add.v4.f32 [%0], {%1, %2, %3, %4};"
                 :: "l"(ap), "f"(w * v.x), "f"(w * v.y), "f"(w * v.z), "f"(w * v.w)
                 : "memory");
}

// ---------------- head: relu(agg + dinv^2*h + b_conv) @ W_lin, softmax -------
__global__ __launch_bounds__(256) void k_head(const float* __restrict__ b_conv,
                                              const float* __restrict__ W_lin,
                                              const float* __restrict__ b_lin,
                                              float* __restrict__ out) {
    int i    = blockIdx.x * 8 + (threadIdx.x >> 5);
    int lane = threadIdx.x & 31;
    if (i >= N_NODES) return;

    float dr = rsqrtf(g_deg[i]);
    float d2 = dr * dr;
    float4 v  = ((const float4*)(g_agg + (size_t)i * HID))[lane];
    float4 hv = ((const float4*)(g_h   + (size_t)i * HID))[lane];
    float4 b  = ((const float4*)b_conv)[lane];
    v.x = fmaxf(v.x + d2 * hv.x + b.x, 0.0f);
    v.y = fmaxf(v.y + d2 * hv.y + b.y, 0.0f);
    v.z = fmaxf(v.z + d2 * hv.z + b.z, 0.0f);
    v.w = fmaxf(v.w + d2 * hv.w + b.w, 0.0f);

    int k = lane * 4;
    float l0 = v.x * W_lin[(k + 0) * 2 + 0] + v.y * W_lin[(k + 1) * 2 + 0] +
               v.z * W_lin[(k + 2) * 2 + 0] + v.w * W_lin[(k + 3) * 2 + 0];
    float l1 = v.x * W_lin[(k + 0) * 2 + 1] + v.y * W_lin[(k + 1) * 2 + 1] +
               v.z * W_lin[(k + 2) * 2 + 1] + v.w * W_lin[(k + 3) * 2 + 1];

#pragma unroll
    for (int off = 16; off > 0; off >>= 1) {
        l0 += __shfl_xor_sync(0xFFFFFFFFu, l0, off);
        l1 += __shfl_xor_sync(0xFFFFFFFFu, l1, off);
    }

    if (lane == 0) {
        l0 += b_lin[0];
        l1 += b_lin[1];
        float m  = fmaxf(l0, l1);
        float e0 = expf(l0 - m), e1 = expf(l1 - m);
        float s  = e0 + e1;
        out[i * 2 + 0] = e0 / s;
        out[i * 2 + 1] = e1 / s;
    }
}

// -----------------------------------------------------------------------------
extern "C" void kernel_launch(void* const* d_in, const int* in_sizes, int n_in,
                              void* d_out, int out_size) {
    const float* x      = (const float*)d_in[0];
    const void*  ei     = d_in[1];                  // int64 or int32 (detected)
    const float* ew     = (const float*)d_in[2];
    const float* W_conv = (const float*)d_in[3];
    const float* b_conv = (const float*)d_in[4];
    const float* W_lin  = (const float*)d_in[5];
    const float* b_lin  = (const float*)d_in[6];
    float* out = (float*)d_out;

    cudaFuncSetAttribute(k_gemm_mma, cudaFuncAttributeMaxDynamicSharedMemorySize,
                         GSMEM);

    k_prep<<<WSPLIT_BLOCKS + 1250, 256>>>(W_conv, (const long long*)ei);
    k_deg_accum<<<(N_EDGES + 255) / 256, 256>>>(ei, ew);
    dim3 gg(KSPL, (N_NODES + BM - 1) / BM);       // (9, 79) = 711 CTAs
    k_gemm_mma<<<gg, 512, GSMEM>>>(x);
    k_scatter<<<(N_EDGES + 7) / 8, 256>>>(ei, ew);
    k_head<<<(N_NODES + 7) / 8, 256>>>(b_conv, W_lin, b_lin, out);
}